// round 3
// baseline (speedup 1.0000x reference)
#include <cuda_runtime.h>
#include <cuda_bf16.h>
#include <math.h>

// Problem constants
#define NN    8192
#define DEG   16
#define FIN   1024
#define FOUT  128
#define NH    8

// GEMM tile config
#define BM 128
#define BN 128
#define BK 16

// Scratch: h[h][n][o], s_dst[h][n], s_src[h][n]
__device__ float g_h[(size_t)NH * NN * FOUT];     // 32 MB
__device__ float g_sd[NH * NN];
__device__ float g_ss[NH * NN];

// ---------------------------------------------------------------------------
// Kernel 1: h = X @ W[hd] + bW[hd]; fused s_dst/s_src epilogue.
// blockIdx.x = row tile (128 rows), blockIdx.y = head (128 cols = full F_OUT)
// 256 threads, 8x8 microtile, packed f32x2 FMAs.
// ---------------------------------------------------------------------------
__global__ __launch_bounds__(256, 2) void gat_gemm(
    const float* __restrict__ X,      // [N, FIN]
    const float* __restrict__ W,      // [H, FIN, FOUT]
    const float* __restrict__ bW,     // [H, FOUT]
    const float* __restrict__ av)     // [H, 2*FOUT]
{
    const int m0 = blockIdx.x * BM;
    const int hd = blockIdx.y;
    const int tid = threadIdx.x;
    const int tx = tid & 15;          // col group 0..15
    const int ty = tid >> 4;          // row group 0..15

    __shared__ __align__(16) float As[BK][BM];
    __shared__ __align__(16) float Bs[BK][BN];

    const float* Wh = W + (size_t)hd * FIN * FOUT;

    // acc as packed f32x2: 8 rows x 4 col-pairs
    unsigned long long acc[8][4];
#pragma unroll
    for (int i = 0; i < 8; i++)
#pragma unroll
        for (int jp = 0; jp < 4; jp++) acc[i][jp] = 0ull;

    for (int k0 = 0; k0 < FIN; k0 += BK) {
        // Load A tile: 128 rows x 16 cols = 512 float4, 2 per thread
#pragma unroll
        for (int p = 0; p < 2; p++) {
            int q = tid + 256 * p;
            int row = q >> 2;             // 0..127
            int kq  = (q & 3) << 2;       // 0,4,8,12
            float4 v = *(const float4*)(X + (size_t)(m0 + row) * FIN + k0 + kq);
            As[kq + 0][row] = v.x;
            As[kq + 1][row] = v.y;
            As[kq + 2][row] = v.z;
            As[kq + 3][row] = v.w;
        }
        // Load B tile: 16 rows x 128 cols = 512 float4, 2 per thread
#pragma unroll
        for (int p = 0; p < 2; p++) {
            int q = tid + 256 * p;
            int fr  = q >> 5;             // 0..15
            int col = (q & 31) << 2;      // 0..124
            float4 v = *(const float4*)(Wh + (size_t)(k0 + fr) * FOUT + col);
            *(float4*)&Bs[fr][col] = v;
        }
        __syncthreads();

#pragma unroll
        for (int kk = 0; kk < BK; kk++) {
            float4 a0 = *(const float4*)&As[kk][ty * 8];
            float4 a1 = *(const float4*)&As[kk][ty * 8 + 4];
            ulonglong2 b0 = *(const ulonglong2*)&Bs[kk][tx * 8];
            ulonglong2 b1 = *(const ulonglong2*)&Bs[kk][tx * 8 + 4];
            float ar[8] = {a0.x, a0.y, a0.z, a0.w, a1.x, a1.y, a1.z, a1.w};
            unsigned long long bp[4] = {b0.x, b0.y, b1.x, b1.y};
#pragma unroll
            for (int i = 0; i < 8; i++) {
                unsigned long long ap;
                asm("mov.b64 %0, {%1, %1};" : "=l"(ap) : "f"(ar[i]));
#pragma unroll
                for (int jp = 0; jp < 4; jp++) {
                    asm("fma.rn.f32x2 %0, %1, %2, %0;"
                        : "+l"(acc[i][jp]) : "l"(ap), "l"(bp[jp]));
                }
            }
        }
        __syncthreads();
    }

    // Epilogue: bias + store h + fused s_dst/s_src dot reduction.
    float bwv[8], adst[8], asrc[8];
#pragma unroll
    for (int j = 0; j < 8; j++) {
        int col = tx * 8 + j;
        bwv[j]  = bW[hd * FOUT + col];
        adst[j] = av[hd * 2 * FOUT + col];
        asrc[j] = av[hd * 2 * FOUT + FOUT + col];
    }

    float* Hh = g_h + (size_t)hd * NN * FOUT;

#pragma unroll
    for (int i = 0; i < 8; i++) {
        int row = m0 + ty * 8 + i;
        float c[8];
#pragma unroll
        for (int jp = 0; jp < 4; jp++) {
            float lo, hi;
            asm("mov.b64 {%0, %1}, %2;" : "=f"(lo), "=f"(hi) : "l"(acc[i][jp]));
            c[jp * 2 + 0] = lo + bwv[jp * 2 + 0];
            c[jp * 2 + 1] = hi + bwv[jp * 2 + 1];
        }
        float pd = 0.f, ps = 0.f;
#pragma unroll
        for (int j = 0; j < 8; j++) {
            pd += c[j] * adst[j];
            ps += c[j] * asrc[j];
        }
        // store 8 floats (2x float4)
        float* dst = Hh + (size_t)row * FOUT + tx * 8;
        *(float4*)(dst + 0) = make_float4(c[0], c[1], c[2], c[3]);
        *(float4*)(dst + 4) = make_float4(c[4], c[5], c[6], c[7]);
        // reduce over the 16 tx lanes (contiguous 16-lane groups in warp)
#pragma unroll
        for (int off = 8; off; off >>= 1) {
            pd += __shfl_xor_sync(0xffffffffu, pd, off);
            ps += __shfl_xor_sync(0xffffffffu, ps, off);
        }
        if (tx == 0) {
            g_sd[hd * NN + row] = pd;
            g_ss[hd * NN + row] = ps;
        }
    }
}

// ---------------------------------------------------------------------------
// Kernel 2: attention softmax + weighted gather.
// block = node n (8192 blocks), warp w = head. 17 neighbors (16 adj + self).
// ---------------------------------------------------------------------------
__global__ __launch_bounds__(256) void gat_attn(
    const int* __restrict__ adj,      // [N, DEG]
    const float* __restrict__ ba,     // [H]
    float* __restrict__ out)          // [N, H*FOUT]
{
    const int n = blockIdx.x;
    const int w = threadIdx.x >> 5;   // head
    const int lane = threadIdx.x & 31;

    const float* Hh = g_h + (size_t)w * NN * FOUT;

    int nbr = n;                      // lane 16 = self; lanes>16 unused
    if (lane < DEG) nbr = adj[n * DEG + lane];

    float sdst = g_sd[w * NN + n];
    float score = -INFINITY;
    if (lane < DEG + 1) {
        float ss = g_ss[w * NN + nbr];
        float s = sdst + ss + ba[w];
        score = (s > 0.f) ? s : 0.2f * s;   // leaky_relu(0.2)
    }
    // warp max
    float mx = score;
#pragma unroll
    for (int off = 16; off; off >>= 1)
        mx = fmaxf(mx, __shfl_xor_sync(0xffffffffu, mx, off));
    float e = (lane < DEG + 1) ? __expf(score - mx) : 0.f;
    float sum = e;
#pragma unroll
    for (int off = 16; off; off >>= 1)
        sum += __shfl_xor_sync(0xffffffffu, sum, off);
    float alpha = e / sum;

    // weighted gather: each lane owns 4 consecutive output features
    float4 accv = make_float4(0.f, 0.f, 0.f, 0.f);
#pragma unroll
    for (int d = 0; d < DEG + 1; d++) {
        float ad = __shfl_sync(0xffffffffu, alpha, d);
        int idx  = __shfl_sync(0xffffffffu, nbr, d);
        float4 v = *(const float4*)(Hh + (size_t)idx * FOUT + lane * 4);
        accv.x += ad * v.x;
        accv.y += ad * v.y;
        accv.z += ad * v.z;
        accv.w += ad * v.w;
    }
    *(float4*)(out + (size_t)n * (NH * FOUT) + w * FOUT + lane * 4) = accv;
}

// ---------------------------------------------------------------------------
extern "C" void kernel_launch(void* const* d_in, const int* in_sizes, int n_in,
                              void* d_out, int out_size)
{
    const float* X   = (const float*)d_in[0];   // features [N, FIN]
    const int*   adj = (const int*)  d_in[1];   // [N, DEG]
    const float* W   = (const float*)d_in[2];   // [H, FIN, FOUT]
    const float* bW  = (const float*)d_in[3];   // [H, FOUT]
    const float* av  = (const float*)d_in[4];   // [H, 2*FOUT]
    const float* ba  = (const float*)d_in[5];   // [H]
    float* out = (float*)d_out;                 // [N, H*FOUT]

    dim3 g1(NN / BM, NH);
    gat_gemm<<<g1, 256>>>(X, W, bW, av);
    gat_attn<<<NN, 256>>>(adj, ba, out);
}

// round 5
// speedup vs baseline: 3.0899x; 3.0899x over previous
#include <cuda_runtime.h>
#include <cuda_bf16.h>
#include <math.h>
#include <stdint.h>

// Problem constants
#define NN    8192
#define DEG   16
#define FIN   1024
#define FOUT  128
#define NH    8

// GEMM config
#define BM 128
#define BN 128
#define BK 32
#define NCH 96            // 3 segments x (FIN/BK)=32 chunks
#define AS_STRIDE 40      // halves per A row (32 + 8 pad)
#define BS_STRIDE 136     // halves per B row (128 + 8 pad)
#define AS_BYTES (BM * AS_STRIDE * 2)          // 10240
#define BS_BYTES (BK * BS_STRIDE * 2)          // 8704
#define STAGE_BYTES (AS_BYTES + BS_BYTES)      // 18944
#define CS_STRIDE 132
#define SMEM_BYTES (BM * CS_STRIDE * 4)        // 67584 (>= 2*STAGE_BYTES)

// ---------------------------------------------------------------------------
// Scratch (device globals — no allocs allowed)
// ---------------------------------------------------------------------------
__device__ float g_h [(size_t)NH * NN * FOUT];    // 32 MB
__device__ float g_sd[NH * NN];
__device__ float g_ss[NH * NN];
__device__ __nv_bfloat16 g_Xhi[(size_t)NN * FIN];         // 16 MB
__device__ __nv_bfloat16 g_Xlo[(size_t)NN * FIN];         // 16 MB
__device__ __nv_bfloat16 g_Whi[(size_t)NH * FIN * FOUT];  // 2 MB  [h][k][n]
__device__ __nv_bfloat16 g_Wlo[(size_t)NH * FIN * FOUT];  // 2 MB

// ---------------------------------------------------------------------------
// helpers
// ---------------------------------------------------------------------------
__device__ __forceinline__ uint32_t smem_u32(const void* p) {
    uint32_t a;
    asm("{ .reg .u64 t; cvta.to.shared.u64 t, %1; cvt.u32.u64 %0, t; }" : "=r"(a) : "l"(p));
    return a;
}
__device__ __forceinline__ void cpasync16(uint32_t dst, const void* src) {
    asm volatile("cp.async.cg.shared.global [%0], [%1], 16;"
                 :: "r"(dst), "l"(__cvta_generic_to_global(src)) : "memory");
}
__device__ __forceinline__ void ldsm_x4(uint32_t* r, uint32_t addr) {
    asm volatile("ldmatrix.sync.aligned.m8n8.x4.shared.b16 {%0,%1,%2,%3}, [%4];"
                 : "=r"(r[0]), "=r"(r[1]), "=r"(r[2]), "=r"(r[3]) : "r"(addr));
}
__device__ __forceinline__ void ldsm_x4_t(uint32_t* r, uint32_t addr) {
    asm volatile("ldmatrix.sync.aligned.m8n8.x4.trans.shared.b16 {%0,%1,%2,%3}, [%4];"
                 : "=r"(r[0]), "=r"(r[1]), "=r"(r[2]), "=r"(r[3]) : "r"(addr));
}
__device__ __forceinline__ void mma_bf16(float* d, const uint32_t* a, const uint32_t* b) {
    asm volatile(
        "mma.sync.aligned.m16n8k16.row.col.f32.bf16.bf16.f32 "
        "{%0,%1,%2,%3}, {%4,%5,%6,%7}, {%8,%9}, {%0,%1,%2,%3};"
        : "+f"(d[0]), "+f"(d[1]), "+f"(d[2]), "+f"(d[3])
        : "r"(a[0]), "r"(a[1]), "r"(a[2]), "r"(a[3]), "r"(b[0]), "r"(b[1]));
}

// ---------------------------------------------------------------------------
// Prep 1: split X -> bf16 hi/lo
// ---------------------------------------------------------------------------
__global__ __launch_bounds__(256) void conv_x(const float* __restrict__ X) {
    size_t i = (size_t)blockIdx.x * 256 + threadIdx.x;   // NN*FIN/4 float4s
    float4 v = ((const float4*)X)[i];
    float xs[4] = {v.x, v.y, v.z, v.w};
    __nv_bfloat16 hi[4], lo[4];
#pragma unroll
    for (int j = 0; j < 4; j++) {
        hi[j] = __float2bfloat16(xs[j]);
        lo[j] = __float2bfloat16(xs[j] - __bfloat162float(hi[j]));
    }
    *(uint2*)(g_Xhi + i * 4) = *(uint2*)hi;
    *(uint2*)(g_Xlo + i * 4) = *(uint2*)lo;
}

// ---------------------------------------------------------------------------
// Prep 2: split W -> bf16 hi/lo (layout preserved: [h][k][n])
// ---------------------------------------------------------------------------
__global__ __launch_bounds__(256) void conv_w(const float* __restrict__ W) {
    size_t i = (size_t)blockIdx.x * 256 + threadIdx.x;   // H*FIN*FOUT/4 float4s
    float4 v = ((const float4*)W)[i];
    float xs[4] = {v.x, v.y, v.z, v.w};
    __nv_bfloat16 hi[4], lo[4];
#pragma unroll
    for (int j = 0; j < 4; j++) {
        hi[j] = __float2bfloat16(xs[j]);
        lo[j] = __float2bfloat16(xs[j] - __bfloat162float(hi[j]));
    }
    *(uint2*)(g_Whi + i * 4) = *(uint2*)hi;
    *(uint2*)(g_Wlo + i * 4) = *(uint2*)lo;
}

// ---------------------------------------------------------------------------
// Main GEMM via mma.sync bf16 split (3 products, K' = 3072).
// grid (NN/128, NH), 256 threads. Double-buffered cp.async.
// Fused epilogue: bias + g_h store + s_dst/s_src row dots.
// ---------------------------------------------------------------------------
__global__ __launch_bounds__(256, 2) void gat_gemm_mma(
    const float* __restrict__ bW, const float* __restrict__ av)
{
    extern __shared__ char smem[];
    const uint32_t sb = smem_u32(smem);
    float* Cs = (float*)smem;

    const int tid = threadIdx.x, wid = tid >> 5, lane = tid & 31;
    const int m0 = blockIdx.x * BM;
    const int hd = blockIdx.y;
    const int mw = (wid & 1) * 64;       // warp m offset
    const int nw = (wid >> 1) * 32;      // warp n offset

    float acc[4][4][4];
#pragma unroll
    for (int a = 0; a < 4; a++)
#pragma unroll
        for (int b = 0; b < 4; b++)
#pragma unroll
            for (int c = 0; c < 4; c++) acc[a][b][c] = 0.f;

    // per-thread load coords
    const int a_row = tid >> 2, a_col = (tid & 3) * 8;        // +256: rows 64..127
    const int b_row = tid >> 4, b_col = (tid & 15) * 8;       // +256: rows 16..31

    auto issue_loads = [&](int i, int st) {
        const int seg = i >> 5;
        const int kk = (i & 31) * BK;
        const __nv_bfloat16* Aseg = (seg < 2) ? g_Xhi : g_Xlo;
        const __nv_bfloat16* Bseg = (seg == 0) ? g_Whi : ((seg == 1) ? g_Wlo : g_Whi);
        const uint32_t as = sb + st * STAGE_BYTES;
        const uint32_t bs = as + AS_BYTES;
#pragma unroll
        for (int p = 0; p < 2; p++) {
            int row = a_row + p * 64;
            cpasync16(as + (row * AS_STRIDE + a_col) * 2,
                      Aseg + (size_t)(m0 + row) * FIN + kk + a_col);
        }
#pragma unroll
        for (int p = 0; p < 2; p++) {
            int row = b_row + p * 16;
            cpasync16(bs + (row * BS_STRIDE + b_col) * 2,
                      Bseg + ((size_t)hd * FIN + kk + row) * FOUT + b_col);
        }
        asm volatile("cp.async.commit_group;" ::: "memory");
    };

    issue_loads(0, 0);

    const int lr = lane & 15, lh = (lane >> 4) << 3;   // ldmatrix addressing

    for (int i = 0; i < NCH; i++) {
        asm volatile("cp.async.wait_group 0;" ::: "memory");
        __syncthreads();
        if (i + 1 < NCH) issue_loads(i + 1, (i + 1) & 1);

        const uint32_t as = sb + (i & 1) * STAGE_BYTES;
        const uint32_t bs = as + AS_BYTES;

#pragma unroll
        for (int ks = 0; ks < 2; ks++) {
            const int k16 = ks * 16;
            uint32_t afr[4][4], bfr[2][4];
#pragma unroll
            for (int mt = 0; mt < 4; mt++)
                ldsm_x4(afr[mt], as + ((mw + mt * 16 + lr) * AS_STRIDE + k16 + lh) * 2);
#pragma unroll
            for (int nt2 = 0; nt2 < 2; nt2++)
                ldsm_x4_t(bfr[nt2], bs + ((k16 + lr) * BS_STRIDE + nw + nt2 * 16 + lh) * 2);
#pragma unroll
            for (int mt = 0; mt < 4; mt++)
#pragma unroll
                for (int nt = 0; nt < 4; nt++)
                    mma_bf16(acc[mt][nt], afr[mt], &bfr[nt >> 1][(nt & 1) * 2]);
        }
        __syncthreads();   // all warps done with this stage before it is refilled
    }

    // ---- epilogue: accum -> smem tile ----
    __syncthreads();
#pragma unroll
    for (int mt = 0; mt < 4; mt++) {
#pragma unroll
        for (int nt = 0; nt < 4; nt++) {
            int row = mw + mt * 16 + (lane >> 2);
            int col = nw + nt * 8 + ((lane & 3) * 2);
            Cs[row * CS_STRIDE + col]           = acc[mt][nt][0];
            Cs[row * CS_STRIDE + col + 1]       = acc[mt][nt][1];
            Cs[(row + 8) * CS_STRIDE + col]     = acc[mt][nt][2];
            Cs[(row + 8) * CS_STRIDE + col + 1] = acc[mt][nt][3];
        }
    }
    __syncthreads();

    // bias + store + fused dots: 2 threads per row, 64 cols each
    {
        const int row = tid >> 1;
        const int c0 = (tid & 1) * 64;
        const float* bWh = bW + hd * FOUT;
        const float* ad  = av + hd * 2 * FOUT;
        const float* as_ = ad + FOUT;
        float* dst = g_h + ((size_t)hd * NN + m0 + row) * FOUT + c0;
        float pd = 0.f, ps = 0.f;
#pragma unroll
        for (int j = 0; j < 64; j += 4) {
            float4 v;
            float t0 = Cs[row * CS_STRIDE + c0 + j + 0] + bWh[c0 + j + 0];
            float t1 = Cs[row * CS_STRIDE + c0 + j + 1] + bWh[c0 + j + 1];
            float t2 = Cs[row * CS_STRIDE + c0 + j + 2] + bWh[c0 + j + 2];
            float t3 = Cs[row * CS_STRIDE + c0 + j + 3] + bWh[c0 + j + 3];
            pd += t0 * ad[c0 + j] + t1 * ad[c0 + j + 1] + t2 * ad[c0 + j + 2] + t3 * ad[c0 + j + 3];
            ps += t0 * as_[c0 + j] + t1 * as_[c0 + j + 1] + t2 * as_[c0 + j + 2] + t3 * as_[c0 + j + 3];
            v.x = t0; v.y = t1; v.z = t2; v.w = t3;
            *(float4*)(dst + j) = v;
        }
        pd += __shfl_xor_sync(0xffffffffu, pd, 1);
        ps += __shfl_xor_sync(0xffffffffu, ps, 1);
        if ((tid & 1) == 0) {
            g_sd[hd * NN + m0 + row] = pd;
            g_ss[hd * NN + m0 + row] = ps;
        }
    }
}

// ---------------------------------------------------------------------------
// Attention softmax + weighted gather
// ---------------------------------------------------------------------------
__global__ __launch_bounds__(256) void gat_attn(
    const int* __restrict__ adj, const float* __restrict__ ba,
    float* __restrict__ out)
{
    const int n = blockIdx.x;
    const int w = threadIdx.x >> 5;
    const int lane = threadIdx.x & 31;

    const float* Hh = g_h + (size_t)w * NN * FOUT;

    int nbr = n;
    if (lane < DEG) nbr = adj[n * DEG + lane];

    float sdst = g_sd[w * NN + n];
    float score = -INFINITY;
    if (lane < DEG + 1) {
        float s = sdst + g_ss[w * NN + nbr] + ba[w];
        score = (s > 0.f) ? s : 0.2f * s;
    }
    float mx = score;
#pragma unroll
    for (int off = 16; off; off >>= 1)
        mx = fmaxf(mx, __shfl_xor_sync(0xffffffffu, mx, off));
    float e = (lane < DEG + 1) ? __expf(score - mx) : 0.f;
    float sum = e;
#pragma unroll
    for (int off = 16; off; off >>= 1)
        sum += __shfl_xor_sync(0xffffffffu, sum, off);
    float alpha = e / sum;

    float4 accv = make_float4(0.f, 0.f, 0.f, 0.f);
#pragma unroll
    for (int d = 0; d < DEG + 1; d++) {
        float ad = __shfl_sync(0xffffffffu, alpha, d);
        int idx  = __shfl_sync(0xffffffffu, nbr, d);
        float4 v = *(const float4*)(Hh + (size_t)idx * FOUT + lane * 4);
        accv.x += ad * v.x; accv.y += ad * v.y;
        accv.z += ad * v.z; accv.w += ad * v.w;
    }
    *(float4*)(out + (size_t)n * (NH * FOUT) + w * FOUT + lane * 4) = accv;
}

// ---------------------------------------------------------------------------
extern "C" void kernel_launch(void* const* d_in, const int* in_sizes, int n_in,
                              void* d_out, int out_size)
{
    const float* X   = (const float*)d_in[0];
    const int*   adj = (const int*)  d_in[1];
    const float* W   = (const float*)d_in[2];
    const float* bW  = (const float*)d_in[3];
    const float* av  = (const float*)d_in[4];
    const float* ba  = (const float*)d_in[5];
    float* out = (float*)d_out;

    static bool attr_set = false;
    if (!attr_set) {
        cudaFuncSetAttribute(gat_gemm_mma,
                             cudaFuncAttributeMaxDynamicSharedMemorySize, SMEM_BYTES);
        attr_set = true;
    }

    conv_x<<<NN * FIN / 4 / 256, 256>>>(X);
    conv_w<<<NH * FIN * FOUT / 4 / 256, 256>>>(W);
    gat_gemm_mma<<<dim3(NN / BM, NH), 256, SMEM_BYTES>>>(bW, av);
    gat_attn<<<NN, 256>>>(adj, ba, out);
}

// round 6
// speedup vs baseline: 4.2362x; 1.3710x over previous
#include <cuda_runtime.h>
#include <cuda_fp16.h>
#include <math.h>
#include <stdint.h>

// Problem constants
#define NN    8192
#define DEG   16
#define FIN   1024
#define FOUT  128
#define NH    8

// GEMM config
#define BM 128
#define BN 128
#define BK 32
#define NCH (FIN / BK)    // 32 chunks; each chunk does hi+lo products vs one B
#define AS_STRIDE 40      // halves per A row (32 + 8 pad)
#define BS_STRIDE 136     // halves per B row (128 + 8 pad)
#define A_BYTES (BM * AS_STRIDE * 2)           // 10240 (one of hi/lo)
#define B_BYTES (BK * BS_STRIDE * 2)           // 8704
#define STAGE_BYTES (2 * A_BYTES + B_BYTES)    // 29184
#define CS_STRIDE 132
#define SMEM_BYTES (BM * CS_STRIDE * 4)        // 67584 (>= 2*STAGE_BYTES)

// ---------------------------------------------------------------------------
// Scratch (device globals — no allocs allowed)
// ---------------------------------------------------------------------------
__device__ float g_h [(size_t)NH * NN * FOUT];    // 32 MB
__device__ float g_sd[NH * NN];
__device__ float g_ss[NH * NN];
__device__ __half g_Xhi[(size_t)NN * FIN];        // 16 MB
__device__ __half g_Xlo[(size_t)NN * FIN];        // 16 MB
__device__ __half g_Wh [(size_t)NH * FIN * FOUT]; // 2 MB  [h][k][n]

// ---------------------------------------------------------------------------
// helpers
// ---------------------------------------------------------------------------
__device__ __forceinline__ uint32_t smem_u32(const void* p) {
    uint32_t a;
    asm("{ .reg .u64 t; cvta.to.shared.u64 t, %1; cvt.u32.u64 %0, t; }" : "=r"(a) : "l"(p));
    return a;
}
__device__ __forceinline__ void cpasync16(uint32_t dst, const void* src) {
    asm volatile("cp.async.cg.shared.global [%0], [%1], 16;"
                 :: "r"(dst), "l"(__cvta_generic_to_global(src)) : "memory");
}
__device__ __forceinline__ void ldsm_x4(uint32_t* r, uint32_t addr) {
    asm volatile("ldmatrix.sync.aligned.m8n8.x4.shared.b16 {%0,%1,%2,%3}, [%4];"
                 : "=r"(r[0]), "=r"(r[1]), "=r"(r[2]), "=r"(r[3]) : "r"(addr));
}
__device__ __forceinline__ void ldsm_x4_t(uint32_t* r, uint32_t addr) {
    asm volatile("ldmatrix.sync.aligned.m8n8.x4.trans.shared.b16 {%0,%1,%2,%3}, [%4];"
                 : "=r"(r[0]), "=r"(r[1]), "=r"(r[2]), "=r"(r[3]) : "r"(addr));
}
__device__ __forceinline__ void mma_f16(float* d, const uint32_t* a, const uint32_t* b) {
    asm volatile(
        "mma.sync.aligned.m16n8k16.row.col.f32.f16.f16.f32 "
        "{%0,%1,%2,%3}, {%4,%5,%6,%7}, {%8,%9}, {%0,%1,%2,%3};"
        : "+f"(d[0]), "+f"(d[1]), "+f"(d[2]), "+f"(d[3])
        : "r"(a[0]), "r"(a[1]), "r"(a[2]), "r"(a[3]), "r"(b[0]), "r"(b[1]));
}

// ---------------------------------------------------------------------------
// Prep 1: split X -> fp16 hi/lo (X = hi + lo to ~2^-22)
// ---------------------------------------------------------------------------
__global__ __launch_bounds__(256) void conv_x(const float* __restrict__ X) {
    size_t i = (size_t)blockIdx.x * 256 + threadIdx.x;   // NN*FIN/4 float4s
    float4 v = ((const float4*)X)[i];
    float xs[4] = {v.x, v.y, v.z, v.w};
    __half hi[4], lo[4];
#pragma unroll
    for (int j = 0; j < 4; j++) {
        hi[j] = __float2half_rn(xs[j]);
        lo[j] = __float2half_rn(xs[j] - __half2float(hi[j]));
    }
    *(uint2*)(g_Xhi + i * 4) = *(uint2*)hi;
    *(uint2*)(g_Xlo + i * 4) = *(uint2*)lo;
}

// ---------------------------------------------------------------------------
// Prep 2: W -> fp16 (layout preserved: [h][k][n])
// ---------------------------------------------------------------------------
__global__ __launch_bounds__(256) void conv_w(const float* __restrict__ W) {
    size_t i = (size_t)blockIdx.x * 256 + threadIdx.x;   // H*FIN*FOUT/4 float4s
    float4 v = ((const float4*)W)[i];
    __half h[4] = { __float2half_rn(v.x), __float2half_rn(v.y),
                    __float2half_rn(v.z), __float2half_rn(v.w) };
    *(uint2*)(g_Wh + i * 4) = *(uint2*)h;
}

// ---------------------------------------------------------------------------
// Main GEMM via mma.sync fp16 2-product split, shared-B chunks.
// grid (NN/128, NH), 256 threads. Double-buffered cp.async.
// Fused epilogue: bias + g_h store + s_dst/s_src row dots.
// ---------------------------------------------------------------------------
__global__ __launch_bounds__(256, 2) void gat_gemm_mma(
    const float* __restrict__ bW, const float* __restrict__ av)
{
    extern __shared__ char smem[];
    const uint32_t sb = smem_u32(smem);
    float* Cs = (float*)smem;

    const int tid = threadIdx.x, wid = tid >> 5, lane = tid & 31;
    const int m0 = blockIdx.x * BM;
    const int hd = blockIdx.y;
    const int mw = (wid & 1) * 64;       // warp m offset
    const int nw = (wid >> 1) * 32;      // warp n offset

    float acc[4][4][4];
#pragma unroll
    for (int a = 0; a < 4; a++)
#pragma unroll
        for (int b = 0; b < 4; b++)
#pragma unroll
            for (int c = 0; c < 4; c++) acc[a][b][c] = 0.f;

    // per-thread load coords
    const int a_row = tid >> 2, a_col = (tid & 3) * 8;        // +64 second half
    const int b_row = tid >> 4, b_col = (tid & 15) * 8;       // +16 second half

    auto issue_loads = [&](int i, int st) {
        const int kk = i * BK;
        const uint32_t ah = sb + st * STAGE_BYTES;
        const uint32_t al = ah + A_BYTES;
        const uint32_t bs = al + A_BYTES;
#pragma unroll
        for (int p = 0; p < 2; p++) {
            int row = a_row + p * 64;
            size_t src = (size_t)(m0 + row) * FIN + kk + a_col;
            uint32_t off = (row * AS_STRIDE + a_col) * 2;
            cpasync16(ah + off, g_Xhi + src);
            cpasync16(al + off, g_Xlo + src);
        }
#pragma unroll
        for (int p = 0; p < 2; p++) {
            int row = b_row + p * 16;
            cpasync16(bs + (row * BS_STRIDE + b_col) * 2,
                      g_Wh + ((size_t)hd * FIN + kk + row) * FOUT + b_col);
        }
        asm volatile("cp.async.commit_group;" ::: "memory");
    };

    issue_loads(0, 0);

    const int lr = lane & 15, lh = (lane >> 4) << 3;   // ldmatrix addressing

    for (int i = 0; i < NCH; i++) {
        asm volatile("cp.async.wait_group 0;" ::: "memory");
        __syncthreads();
        if (i + 1 < NCH) issue_loads(i + 1, (i + 1) & 1);

        const uint32_t ah = sb + (i & 1) * STAGE_BYTES;
        const uint32_t al = ah + A_BYTES;
        const uint32_t bs = al + A_BYTES;

#pragma unroll
        for (int ks = 0; ks < 2; ks++) {
            const int k16 = ks * 16;
            uint32_t ahf[4][4], alf[4][4], bfr[2][4];
#pragma unroll
            for (int mt = 0; mt < 4; mt++) {
                uint32_t roff = ((mw + mt * 16 + lr) * AS_STRIDE + k16 + lh) * 2;
                ldsm_x4(ahf[mt], ah + roff);
                ldsm_x4(alf[mt], al + roff);
            }
#pragma unroll
            for (int nt2 = 0; nt2 < 2; nt2++)
                ldsm_x4_t(bfr[nt2], bs + ((k16 + lr) * BS_STRIDE + nw + nt2 * 16 + lh) * 2);
#pragma unroll
            for (int mt = 0; mt < 4; mt++)
#pragma unroll
                for (int nt = 0; nt < 4; nt++) {
                    mma_f16(acc[mt][nt], ahf[mt], &bfr[nt >> 1][(nt & 1) * 2]);
                    mma_f16(acc[mt][nt], alf[mt], &bfr[nt >> 1][(nt & 1) * 2]);
                }
        }
        __syncthreads();   // all warps done with this stage before refill
    }

    // ---- epilogue: accum -> smem tile ----
    __syncthreads();
#pragma unroll
    for (int mt = 0; mt < 4; mt++) {
#pragma unroll
        for (int nt = 0; nt < 4; nt++) {
            int row = mw + mt * 16 + (lane >> 2);
            int col = nw + nt * 8 + ((lane & 3) * 2);
            Cs[row * CS_STRIDE + col]           = acc[mt][nt][0];
            Cs[row * CS_STRIDE + col + 1]       = acc[mt][nt][1];
            Cs[(row + 8) * CS_STRIDE + col]     = acc[mt][nt][2];
            Cs[(row + 8) * CS_STRIDE + col + 1] = acc[mt][nt][3];
        }
    }
    __syncthreads();

    // bias + store + fused dots: 2 threads per row, 64 cols each
    {
        const int row = tid >> 1;
        const int c0 = (tid & 1) * 64;
        const float* bWh = bW + hd * FOUT;
        const float* ad  = av + hd * 2 * FOUT;
        const float* as_ = ad + FOUT;
        float* dst = g_h + ((size_t)hd * NN + m0 + row) * FOUT + c0;
        float pd = 0.f, ps = 0.f;
#pragma unroll
        for (int j = 0; j < 64; j += 4) {
            float4 v;
            float t0 = Cs[row * CS_STRIDE + c0 + j + 0] + bWh[c0 + j + 0];
            float t1 = Cs[row * CS_STRIDE + c0 + j + 1] + bWh[c0 + j + 1];
            float t2 = Cs[row * CS_STRIDE + c0 + j + 2] + bWh[c0 + j + 2];
            float t3 = Cs[row * CS_STRIDE + c0 + j + 3] + bWh[c0 + j + 3];
            pd += t0 * ad[c0 + j] + t1 * ad[c0 + j + 1] + t2 * ad[c0 + j + 2] + t3 * ad[c0 + j + 3];
            ps += t0 * as_[c0 + j] + t1 * as_[c0 + j + 1] + t2 * as_[c0 + j + 2] + t3 * as_[c0 + j + 3];
            v.x = t0; v.y = t1; v.z = t2; v.w = t3;
            *(float4*)(dst + j) = v;
        }
        pd += __shfl_xor_sync(0xffffffffu, pd, 1);
        ps += __shfl_xor_sync(0xffffffffu, ps, 1);
        if ((tid & 1) == 0) {
            g_sd[hd * NN + m0 + row] = pd;
            g_ss[hd * NN + m0 + row] = ps;
        }
    }
}

// ---------------------------------------------------------------------------
// Attention softmax + weighted gather
// ---------------------------------------------------------------------------
__global__ __launch_bounds__(256) void gat_attn(
    const int* __restrict__ adj, const float* __restrict__ ba,
    float* __restrict__ out)
{
    const int n = blockIdx.x;
    const int w = threadIdx.x >> 5;
    const int lane = threadIdx.x & 31;

    const float* Hh = g_h + (size_t)w * NN * FOUT;

    int nbr = n;
    if (lane < DEG) nbr = adj[n * DEG + lane];

    float sdst = g_sd[w * NN + n];
    float score = -INFINITY;
    if (lane < DEG + 1) {
        float s = sdst + g_ss[w * NN + nbr] + ba[w];
        score = (s > 0.f) ? s : 0.2f * s;
    }
    float mx = score;
#pragma unroll
    for (int off = 16; off; off >>= 1)
        mx = fmaxf(mx, __shfl_xor_sync(0xffffffffu, mx, off));
    float e = (lane < DEG + 1) ? __expf(score - mx) : 0.f;
    float sum = e;
#pragma unroll
    for (int off = 16; off; off >>= 1)
        sum += __shfl_xor_sync(0xffffffffu, sum, off);
    float alpha = e / sum;

    float4 accv = make_float4(0.f, 0.f, 0.f, 0.f);
#pragma unroll
    for (int d = 0; d < DEG + 1; d++) {
        float ad = __shfl_sync(0xffffffffu, alpha, d);
        int idx  = __shfl_sync(0xffffffffu, nbr, d);
        float4 v = *(const float4*)(Hh + (size_t)idx * FOUT + lane * 4);
        accv.x += ad * v.x; accv.y += ad * v.y;
        accv.z += ad * v.z; accv.w += ad * v.w;
    }
    *(float4*)(out + (size_t)n * (NH * FOUT) + w * FOUT + lane * 4) = accv;
}

// ---------------------------------------------------------------------------
extern "C" void kernel_launch(void* const* d_in, const int* in_sizes, int n_in,
                              void* d_out, int out_size)
{
    const float* X   = (const float*)d_in[0];
    const int*   adj = (const int*)  d_in[1];
    const float* W   = (const float*)d_in[2];
    const float* bW  = (const float*)d_in[3];
    const float* av  = (const float*)d_in[4];
    const float* ba  = (const float*)d_in[5];
    float* out = (float*)d_out;

    cudaFuncSetAttribute(gat_gemm_mma,
                         cudaFuncAttributeMaxDynamicSharedMemorySize, SMEM_BYTES);

    conv_x<<<NN * FIN / 4 / 256, 256>>>(X);
    conv_w<<<NH * FIN * FOUT / 4 / 256, 256>>>(W);
    gat_gemm_mma<<<dim3(NN / BM, NH), 256, SMEM_BYTES>>>(bW, av);
    gat_attn<<<NN, 256>>>(adj, ba, out);
}

// round 8
// speedup vs baseline: 5.8961x; 1.3918x over previous
#include <cuda_runtime.h>
#include <cuda_fp16.h>
#include <math.h>
#include <stdint.h>

// Problem constants
#define NN    8192
#define DEG   16
#define FIN   1024
#define FOUT  128
#define NH    8

// GEMM config
#define BM 128
#define BN 128
#define BK 32
#define NCH (FIN / BK)    // 32 chunks
#define AS_STRIDE 40      // halves per A row (32 + 8 pad)
#define BS_STRIDE 136     // halves per B row (128 + 8 pad)
#define A_BYTES (BM * AS_STRIDE * 2)           // 10240
#define B_BYTES (BK * BS_STRIDE * 2)           // 8704
#define STAGE_BYTES (A_BYTES + B_BYTES)        // 18944
#define CS_STRIDE 132
#define SMEM_BYTES (BM * CS_STRIDE * 4)        // 67584 (>= 2*STAGE_BYTES)

// ---------------------------------------------------------------------------
// Scratch (device globals — no allocs allowed)
// ---------------------------------------------------------------------------
__device__ float g_h [(size_t)NH * NN * FOUT];    // 32 MB
__device__ float g_sd[NH * NN];
__device__ float g_ss[NH * NN];
__device__ __half g_Xh[(size_t)NN * FIN];         // 16 MB
__device__ __half g_Wh[(size_t)NH * FIN * FOUT];  // 2 MB  [h][k][n]

// ---------------------------------------------------------------------------
// helpers
// ---------------------------------------------------------------------------
__device__ __forceinline__ uint32_t smem_u32(const void* p) {
    uint32_t a;
    asm("{ .reg .u64 t; cvta.to.shared.u64 t, %1; cvt.u32.u64 %0, t; }" : "=r"(a) : "l"(p));
    return a;
}
__device__ __forceinline__ void cpasync16(uint32_t dst, const void* src) {
    asm volatile("cp.async.cg.shared.global [%0], [%1], 16;"
                 :: "r"(dst), "l"(__cvta_generic_to_global(src)) : "memory");
}
__device__ __forceinline__ void ldsm_x4(uint32_t* r, uint32_t addr) {
    asm volatile("ldmatrix.sync.aligned.m8n8.x4.shared.b16 {%0,%1,%2,%3}, [%4];"
                 : "=r"(r[0]), "=r"(r[1]), "=r"(r[2]), "=r"(r[3]) : "r"(addr));
}
__device__ __forceinline__ void ldsm_x4_t(uint32_t* r, uint32_t addr) {
    asm volatile("ldmatrix.sync.aligned.m8n8.x4.trans.shared.b16 {%0,%1,%2,%3}, [%4];"
                 : "=r"(r[0]), "=r"(r[1]), "=r"(r[2]), "=r"(r[3]) : "r"(addr));
}
__device__ __forceinline__ void mma_f16(float* d, const uint32_t* a, const uint32_t* b) {
    asm volatile(
        "mma.sync.aligned.m16n8k16.row.col.f32.f16.f16.f32 "
        "{%0,%1,%2,%3}, {%4,%5,%6,%7}, {%8,%9}, {%0,%1,%2,%3};"
        : "+f"(d[0]), "+f"(d[1]), "+f"(d[2]), "+f"(d[3])
        : "r"(a[0]), "r"(a[1]), "r"(a[2]), "r"(a[3]), "r"(b[0]), "r"(b[1]));
}

// ---------------------------------------------------------------------------
// Prep 1: X -> fp16
// ---------------------------------------------------------------------------
__global__ __launch_bounds__(256) void conv_x(const float* __restrict__ X) {
    size_t i = (size_t)blockIdx.x * 256 + threadIdx.x;   // NN*FIN/4 float4s
    float4 v = ((const float4*)X)[i];
    __half h[4] = { __float2half_rn(v.x), __float2half_rn(v.y),
                    __float2half_rn(v.z), __float2half_rn(v.w) };
    *(uint2*)(g_Xh + i * 4) = *(uint2*)h;
}

// ---------------------------------------------------------------------------
// Prep 2: W -> fp16 (layout preserved: [h][k][n])
// ---------------------------------------------------------------------------
__global__ __launch_bounds__(256) void conv_w(const float* __restrict__ W) {
    size_t i = (size_t)blockIdx.x * 256 + threadIdx.x;   // H*FIN*FOUT/4 float4s
    float4 v = ((const float4*)W)[i];
    __half h[4] = { __float2half_rn(v.x), __float2half_rn(v.y),
                    __float2half_rn(v.z), __float2half_rn(v.w) };
    *(uint2*)(g_Wh + i * 4) = *(uint2*)h;
}

// ---------------------------------------------------------------------------
// Main GEMM via mma.sync fp16, single product.
// grid (NN/128, NH), 256 threads. Double-buffered cp.async.
// Fused epilogue: bias + g_h store + s_dst/s_src row dots.
// ---------------------------------------------------------------------------
__global__ __launch_bounds__(256, 2) void gat_gemm_mma(
    const float* __restrict__ bW, const float* __restrict__ av)
{
    extern __shared__ char smem[];
    const uint32_t sb = smem_u32(smem);
    float* Cs = (float*)smem;

    const int tid = threadIdx.x, wid = tid >> 5, lane = tid & 31;
    const int m0 = blockIdx.x * BM;
    const int hd = blockIdx.y;
    const int mw = (wid & 1) * 64;       // warp m offset
    const int nw = (wid >> 1) * 32;      // warp n offset

    float acc[4][4][4];
#pragma unroll
    for (int a = 0; a < 4; a++)
#pragma unroll
        for (int b = 0; b < 4; b++)
#pragma unroll
            for (int c = 0; c < 4; c++) acc[a][b][c] = 0.f;

    // per-thread load coords
    const int a_row = tid >> 2, a_col = (tid & 3) * 8;        // +64 second half
    const int b_row = tid >> 4, b_col = (tid & 15) * 8;       // +16 second half

    auto issue_loads = [&](int i, int st) {
        const int kk = i * BK;
        const uint32_t as = sb + st * STAGE_BYTES;
        const uint32_t bs = as + A_BYTES;
#pragma unroll
        for (int p = 0; p < 2; p++) {
            int row = a_row + p * 64;
            cpasync16(as + (row * AS_STRIDE + a_col) * 2,
                      g_Xh + (size_t)(m0 + row) * FIN + kk + a_col);
        }
#pragma unroll
        for (int p = 0; p < 2; p++) {
            int row = b_row + p * 16;
            cpasync16(bs + (row * BS_STRIDE + b_col) * 2,
                      g_Wh + ((size_t)hd * FIN + kk + row) * FOUT + b_col);
        }
        asm volatile("cp.async.commit_group;" ::: "memory");
    };

    issue_loads(0, 0);

    const int lr = lane & 15, lh = (lane >> 4) << 3;   // ldmatrix addressing

    for (int i = 0; i < NCH; i++) {
        asm volatile("cp.async.wait_group 0;" ::: "memory");
        __syncthreads();
        if (i + 1 < NCH) issue_loads(i + 1, (i + 1) & 1);

        const uint32_t as = sb + (i & 1) * STAGE_BYTES;
        const uint32_t bs = as + A_BYTES;

#pragma unroll
        for (int ks = 0; ks < 2; ks++) {
            const int k16 = ks * 16;
            uint32_t afr[4][4], bfr[2][4];
#pragma unroll
            for (int mt = 0; mt < 4; mt++)
                ldsm_x4(afr[mt], as + ((mw + mt * 16 + lr) * AS_STRIDE + k16 + lh) * 2);
#pragma unroll
            for (int nt2 = 0; nt2 < 2; nt2++)
                ldsm_x4_t(bfr[nt2], bs + ((k16 + lr) * BS_STRIDE + nw + nt2 * 16 + lh) * 2);
#pragma unroll
            for (int mt = 0; mt < 4; mt++)
#pragma unroll
                for (int nt = 0; nt < 4; nt++)
                    mma_f16(acc[mt][nt], afr[mt], &bfr[nt >> 1][(nt & 1) * 2]);
        }
        __syncthreads();   // all warps done with this stage before refill
    }

    // ---- epilogue: accum -> smem tile ----
    __syncthreads();
#pragma unroll
    for (int mt = 0; mt < 4; mt++) {
#pragma unroll
        for (int nt = 0; nt < 4; nt++) {
            int row = mw + mt * 16 + (lane >> 2);
            int col = nw + nt * 8 + ((lane & 3) * 2);
            Cs[row * CS_STRIDE + col]           = acc[mt][nt][0];
            Cs[row * CS_STRIDE + col + 1]       = acc[mt][nt][1];
            Cs[(row + 8) * CS_STRIDE + col]     = acc[mt][nt][2];
            Cs[(row + 8) * CS_STRIDE + col + 1] = acc[mt][nt][3];
        }
    }
    __syncthreads();

    // bias + store + fused dots: 2 threads per row, 64 cols each
    {
        const int row = tid >> 1;
        const int c0 = (tid & 1) * 64;
        const float* bWh = bW + hd * FOUT;
        const float* ad  = av + hd * 2 * FOUT;
        const float* as_ = ad + FOUT;
        float* dst = g_h + ((size_t)hd * NN + m0 + row) * FOUT + c0;
        float pd = 0.f, ps = 0.f;
#pragma unroll
        for (int j = 0; j < 64; j += 4) {
            float4 v;
            float t0 = Cs[row * CS_STRIDE + c0 + j + 0] + bWh[c0 + j + 0];
            float t1 = Cs[row * CS_STRIDE + c0 + j + 1] + bWh[c0 + j + 1];
            float t2 = Cs[row * CS_STRIDE + c0 + j + 2] + bWh[c0 + j + 2];
            float t3 = Cs[row * CS_STRIDE + c0 + j + 3] + bWh[c0 + j + 3];
            pd += t0 * ad[c0 + j] + t1 * ad[c0 + j + 1] + t2 * ad[c0 + j + 2] + t3 * ad[c0 + j + 3];
            ps += t0 * as_[c0 + j] + t1 * as_[c0 + j + 1] + t2 * as_[c0 + j + 2] + t3 * as_[c0 + j + 3];
            v.x = t0; v.y = t1; v.z = t2; v.w = t3;
            *(float4*)(dst + j) = v;
        }
        pd += __shfl_xor_sync(0xffffffffu, pd, 1);
        ps += __shfl_xor_sync(0xffffffffu, ps, 1);
        if ((tid & 1) == 0) {
            g_sd[hd * NN + m0 + row] = pd;
            g_ss[hd * NN + m0 + row] = ps;
        }
    }
}

// ---------------------------------------------------------------------------
// Attention softmax + weighted gather
// ---------------------------------------------------------------------------
__global__ __launch_bounds__(256) void gat_attn(
    const int* __restrict__ adj, const float* __restrict__ ba,
    float* __restrict__ out)
{
    const int n = blockIdx.x;
    const int w = threadIdx.x >> 5;
    const int lane = threadIdx.x & 31;

    const float* Hh = g_h + (size_t)w * NN * FOUT;

    int nbr = n;
    if (lane < DEG) nbr = adj[n * DEG + lane];

    float sdst = g_sd[w * NN + n];
    float score = -INFINITY;
    if (lane < DEG + 1) {
        float s = sdst + g_ss[w * NN + nbr] + ba[w];
        score = (s > 0.f) ? s : 0.2f * s;
    }
    float mx = score;
#pragma unroll
    for (int off = 16; off; off >>= 1)
        mx = fmaxf(mx, __shfl_xor_sync(0xffffffffu, mx, off));
    float e = (lane < DEG + 1) ? __expf(score - mx) : 0.f;
    float sum = e;
#pragma unroll
    for (int off = 16; off; off >>= 1)
        sum += __shfl_xor_sync(0xffffffffu, sum, off);
    float alpha = e / sum;

    float4 accv = make_float4(0.f, 0.f, 0.f, 0.f);
#pragma unroll
    for (int d = 0; d < DEG + 1; d++) {
        float ad = __shfl_sync(0xffffffffu, alpha, d);
        int idx  = __shfl_sync(0xffffffffu, nbr, d);
        float4 v = *(const float4*)(Hh + (size_t)idx * FOUT + lane * 4);
        accv.x += ad * v.x; accv.y += ad * v.y;
        accv.z += ad * v.z; accv.w += ad * v.w;
    }
    *(float4*)(out + (size_t)n * (NH * FOUT) + w * FOUT + lane * 4) = accv;
}

// ---------------------------------------------------------------------------
extern "C" void kernel_launch(void* const* d_in, const int* in_sizes, int n_in,
                              void* d_out, int out_size)
{
    const float* X   = (const float*)d_in[0];
    const int*   adj = (const int*)  d_in[1];
    const float* W   = (const float*)d_in[2];
    const float* bW  = (const float*)d_in[3];
    const float* av  = (const float*)d_in[4];
    const float* ba  = (const float*)d_in[5];
    float* out = (float*)d_out;

    cudaFuncSetAttribute(gat_gemm_mma,
                         cudaFuncAttributeMaxDynamicSharedMemorySize, SMEM_BYTES);

    conv_x<<<NN * FIN / 4 / 256, 256>>>(X);
    conv_w<<<NH * FIN * FOUT / 4 / 256, 256>>>(W);
    gat_gemm_mma<<<dim3(NN / BM, NH), 256, SMEM_BYTES>>>(bW, av);
    gat_attn<<<NN, 256>>>(adj, ba, out);
}

// round 10
// speedup vs baseline: 6.5982x; 1.1191x over previous
#include <cuda_runtime.h>
#include <cuda_fp16.h>
#include <math.h>
#include <stdint.h>

// Problem constants
#define NN    8192
#define DEG   16
#define FIN   1024
#define FOUT  128
#define NH    8

// GEMM config
#define BM 128
#define BN 128
#define BK 32
#define NCH (FIN / BK)    // 32 chunks
#define NSTAGE 3
#define AS_STRIDE 40      // halves per A row (32 + 8 pad)
#define BS_STRIDE 136     // halves per B row (128 + 8 pad)
#define A_BYTES (BM * AS_STRIDE * 2)           // 10240
#define B_BYTES (BK * BS_STRIDE * 2)           // 8704
#define STAGE_BYTES (A_BYTES + B_BYTES)        // 18944
#define CS_STRIDE 132
#define SMEM_BYTES (BM * CS_STRIDE * 4)        // 67584 (>= 3*STAGE_BYTES=56832)

// ---------------------------------------------------------------------------
// Scratch (device globals — no allocs allowed)
// ---------------------------------------------------------------------------
__device__ __half g_hh[(size_t)NH * NN * FOUT];   // 16 MB (h in fp16)
__device__ float g_sd[NH * NN];
__device__ float g_ss[NH * NN];
__device__ __half g_Xh[(size_t)NN * FIN];         // 16 MB
__device__ __half g_Wh[(size_t)NH * FIN * FOUT];  // 2 MB  [h][k][n]

// ---------------------------------------------------------------------------
// helpers
// ---------------------------------------------------------------------------
__device__ __forceinline__ uint32_t smem_u32(const void* p) {
    uint32_t a;
    asm("{ .reg .u64 t; cvta.to.shared.u64 t, %1; cvt.u32.u64 %0, t; }" : "=r"(a) : "l"(p));
    return a;
}
__device__ __forceinline__ void cpasync16(uint32_t dst, const void* src) {
    asm volatile("cp.async.cg.shared.global [%0], [%1], 16;"
                 :: "r"(dst), "l"(__cvta_generic_to_global(src)) : "memory");
}
__device__ __forceinline__ void ldsm_x4(uint32_t* r, uint32_t addr) {
    asm volatile("ldmatrix.sync.aligned.m8n8.x4.shared.b16 {%0,%1,%2,%3}, [%4];"
                 : "=r"(r[0]), "=r"(r[1]), "=r"(r[2]), "=r"(r[3]) : "r"(addr));
}
__device__ __forceinline__ void ldsm_x4_t(uint32_t* r, uint32_t addr) {
    asm volatile("ldmatrix.sync.aligned.m8n8.x4.trans.shared.b16 {%0,%1,%2,%3}, [%4];"
                 : "=r"(r[0]), "=r"(r[1]), "=r"(r[2]), "=r"(r[3]) : "r"(addr));
}
__device__ __forceinline__ void mma_f16(float* d, const uint32_t* a, const uint32_t* b) {
    asm volatile(
        "mma.sync.aligned.m16n8k16.row.col.f32.f16.f16.f32 "
        "{%0,%1,%2,%3}, {%4,%5,%6,%7}, {%8,%9}, {%0,%1,%2,%3};"
        : "+f"(d[0]), "+f"(d[1]), "+f"(d[2]), "+f"(d[3])
        : "r"(a[0]), "r"(a[1]), "r"(a[2]), "r"(a[3]), "r"(b[0]), "r"(b[1]));
}

// ---------------------------------------------------------------------------
// Prep 1: X -> fp16
// ---------------------------------------------------------------------------
__global__ __launch_bounds__(256) void conv_x(const float* __restrict__ X) {
    size_t i = (size_t)blockIdx.x * 256 + threadIdx.x;   // NN*FIN/4 float4s
    float4 v = ((const float4*)X)[i];
    __half h[4] = { __float2half_rn(v.x), __float2half_rn(v.y),
                    __float2half_rn(v.z), __float2half_rn(v.w) };
    *(uint2*)(g_Xh + i * 4) = *(uint2*)h;
}

// ---------------------------------------------------------------------------
// Prep 2: W -> fp16 (layout preserved: [h][k][n])
// ---------------------------------------------------------------------------
__global__ __launch_bounds__(256) void conv_w(const float* __restrict__ W) {
    size_t i = (size_t)blockIdx.x * 256 + threadIdx.x;   // H*FIN*FOUT/4 float4s
    float4 v = ((const float4*)W)[i];
    __half h[4] = { __float2half_rn(v.x), __float2half_rn(v.y),
                    __float2half_rn(v.z), __float2half_rn(v.w) };
    *(uint2*)(g_Wh + i * 4) = *(uint2*)h;
}

// ---------------------------------------------------------------------------
// Main GEMM via mma.sync fp16, 3-stage cp.async pipeline.
// grid (NN/128, NH), 256 threads.
// Fused epilogue: bias + fp16 h store + s_dst/s_src row dots (fp32).
// ---------------------------------------------------------------------------
__global__ __launch_bounds__(256, 2) void gat_gemm_mma(
    const float* __restrict__ bW, const float* __restrict__ av)
{
    extern __shared__ char smem[];
    const uint32_t sb = smem_u32(smem);
    float* Cs = (float*)smem;

    const int tid = threadIdx.x, wid = tid >> 5, lane = tid & 31;
    const int m0 = blockIdx.x * BM;
    const int hd = blockIdx.y;
    const int mw = (wid & 1) * 64;       // warp m offset
    const int nw = (wid >> 1) * 32;      // warp n offset

    float acc[4][4][4];
#pragma unroll
    for (int a = 0; a < 4; a++)
#pragma unroll
        for (int b = 0; b < 4; b++)
#pragma unroll
            for (int c = 0; c < 4; c++) acc[a][b][c] = 0.f;

    // per-thread load coords
    const int a_row = tid >> 2, a_col = (tid & 3) * 8;        // +64 second half
    const int b_row = tid >> 4, b_col = (tid & 15) * 8;       // +16 second half

    auto issue_loads = [&](int i) {
        const int kk = i * BK;
        const uint32_t as = sb + (i % NSTAGE) * STAGE_BYTES;
        const uint32_t bs = as + A_BYTES;
#pragma unroll
        for (int p = 0; p < 2; p++) {
            int row = a_row + p * 64;
            cpasync16(as + (row * AS_STRIDE + a_col) * 2,
                      g_Xh + (size_t)(m0 + row) * FIN + kk + a_col);
        }
#pragma unroll
        for (int p = 0; p < 2; p++) {
            int row = b_row + p * 16;
            cpasync16(bs + (row * BS_STRIDE + b_col) * 2,
                      g_Wh + ((size_t)hd * FIN + kk + row) * FOUT + b_col);
        }
        asm volatile("cp.async.commit_group;" ::: "memory");
    };

    issue_loads(0);
    issue_loads(1);

    const int lr = lane & 15, lh = (lane >> 4) << 3;   // ldmatrix addressing

    for (int i = 0; i < NCH; i++) {
        asm volatile("cp.async.wait_group 1;" ::: "memory");
        __syncthreads();
        if (i + 2 < NCH) issue_loads(i + 2);
        else asm volatile("cp.async.commit_group;" ::: "memory");  // keep count

        const uint32_t as = sb + (i % NSTAGE) * STAGE_BYTES;
        const uint32_t bs = as + A_BYTES;

#pragma unroll
        for (int ks = 0; ks < 2; ks++) {
            const int k16 = ks * 16;
            uint32_t afr[4][4], bfr[2][4];
#pragma unroll
            for (int mt = 0; mt < 4; mt++)
                ldsm_x4(afr[mt], as + ((mw + mt * 16 + lr) * AS_STRIDE + k16 + lh) * 2);
#pragma unroll
            for (int nt2 = 0; nt2 < 2; nt2++)
                ldsm_x4_t(bfr[nt2], bs + ((k16 + lr) * BS_STRIDE + nw + nt2 * 16 + lh) * 2);
#pragma unroll
            for (int mt = 0; mt < 4; mt++)
#pragma unroll
                for (int nt = 0; nt < 4; nt++)
                    mma_f16(acc[mt][nt], afr[mt], &bfr[nt >> 1][(nt & 1) * 2]);
        }
    }

    // ---- epilogue: accum -> smem tile ----
    __syncthreads();
#pragma unroll
    for (int mt = 0; mt < 4; mt++) {
#pragma unroll
        for (int nt = 0; nt < 4; nt++) {
            int row = mw + mt * 16 + (lane >> 2);
            int col = nw + nt * 8 + ((lane & 3) * 2);
            Cs[row * CS_STRIDE + col]           = acc[mt][nt][0];
            Cs[row * CS_STRIDE + col + 1]       = acc[mt][nt][1];
            Cs[(row + 8) * CS_STRIDE + col]     = acc[mt][nt][2];
            Cs[(row + 8) * CS_STRIDE + col + 1] = acc[mt][nt][3];
        }
    }
    __syncthreads();

    // bias + fp16 store + fused dots: 2 threads per row, 64 cols each
    {
        const int row = tid >> 1;
        const int c0 = (tid & 1) * 64;
        const float* bWh = bW + hd * FOUT;
        const float* ad  = av + hd * 2 * FOUT;
        const float* as_ = ad + FOUT;
        __half* dst = g_hh + ((size_t)hd * NN + m0 + row) * FOUT + c0;
        float pd = 0.f, ps = 0.f;
#pragma unroll
        for (int j = 0; j < 64; j += 8) {
            float t[8];
#pragma unroll
            for (int q = 0; q < 8; q++) {
                t[q] = Cs[row * CS_STRIDE + c0 + j + q] + bWh[c0 + j + q];
                pd += t[q] * ad[c0 + j + q];
                ps += t[q] * as_[c0 + j + q];
            }
            __half2 h0 = __floats2half2_rn(t[0], t[1]);
            __half2 h1 = __floats2half2_rn(t[2], t[3]);
            __half2 h2 = __floats2half2_rn(t[4], t[5]);
            __half2 h3 = __floats2half2_rn(t[6], t[7]);
            uint4 pk;
            pk.x = *(uint32_t*)&h0; pk.y = *(uint32_t*)&h1;
            pk.z = *(uint32_t*)&h2; pk.w = *(uint32_t*)&h3;
            *(uint4*)(dst + j) = pk;
        }
        pd += __shfl_xor_sync(0xffffffffu, pd, 1);
        ps += __shfl_xor_sync(0xffffffffu, ps, 1);
        if ((tid & 1) == 0) {
            g_sd[hd * NN + m0 + row] = pd;
            g_ss[hd * NN + m0 + row] = ps;
        }
    }
}

// ---------------------------------------------------------------------------
// Attention softmax + weighted gather (h in fp16)
// ---------------------------------------------------------------------------
__global__ __launch_bounds__(256) void gat_attn(
    const int* __restrict__ adj, const float* __restrict__ ba,
    float* __restrict__ out)
{
    const int n = blockIdx.x;
    const int w = threadIdx.x >> 5;
    const int lane = threadIdx.x & 31;

    const __half* Hh = g_hh + (size_t)w * NN * FOUT;

    int nbr = n;
    if (lane < DEG) nbr = adj[n * DEG + lane];

    float sdst = g_sd[w * NN + n];
    float score = -INFINITY;
    if (lane < DEG + 1) {
        float s = sdst + g_ss[w * NN + nbr] + ba[w];
        score = (s > 0.f) ? s : 0.2f * s;
    }
    float mx = score;
#pragma unroll
    for (int off = 16; off; off >>= 1)
        mx = fmaxf(mx, __shfl_xor_sync(0xffffffffu, mx, off));
    float e = (lane < DEG + 1) ? __expf(score - mx) : 0.f;
    float sum = e;
#pragma unroll
    for (int off = 16; off; off >>= 1)
        sum += __shfl_xor_sync(0xffffffffu, sum, off);
    float alpha = e / sum;

    float a0 = 0.f, a1 = 0.f, a2 = 0.f, a3 = 0.f;
#pragma unroll
    for (int d = 0; d < DEG + 1; d++) {
        float ad = __shfl_sync(0xffffffffu, alpha, d);
        int idx  = __shfl_sync(0xffffffffu, nbr, d);
        uint2 v = *(const uint2*)(Hh + (size_t)idx * FOUT + lane * 4);
        float2 f0 = __half22float2(*(__half2*)&v.x);
        float2 f1 = __half22float2(*(__half2*)&v.y);
        a0 += ad * f0.x; a1 += ad * f0.y;
        a2 += ad * f1.x; a3 += ad * f1.y;
    }
    *(float4*)(out + (size_t)n * (NH * FOUT) + w * FOUT + lane * 4) =
        make_float4(a0, a1, a2, a3);
}

// ---------------------------------------------------------------------------
extern "C" void kernel_launch(void* const* d_in, const int* in_sizes, int n_in,
                              void* d_out, int out_size)
{
    const float* X   = (const float*)d_in[0];
    const int*   adj = (const int*)  d_in[1];
    const float* W   = (const float*)d_in[2];
    const float* bW  = (const float*)d_in[3];
    const float* av  = (const float*)d_in[4];
    const float* ba  = (const float*)d_in[5];
    float* out = (float*)d_out;

    cudaFuncSetAttribute(gat_gemm_mma,
                         cudaFuncAttributeMaxDynamicSharedMemorySize, SMEM_BYTES);

    conv_x<<<NN * FIN / 4 / 256, 256>>>(X);
    conv_w<<<NH * FIN * FOUT / 4 / 256, 256>>>(W);
    gat_gemm_mma<<<dim3(NN / BM, NH), 256, SMEM_BYTES>>>(bW, av);
    gat_attn<<<NN, 256>>>(adj, ba, out);
}

// round 13
// speedup vs baseline: 6.7370x; 1.0210x over previous
#include <cuda_runtime.h>
#include <cuda_fp16.h>
#include <math.h>
#include <stdint.h>

// Problem constants
#define NN    8192
#define DEG   16
#define FIN   1024
#define FOUT  128
#define NH    8

// GEMM config: CTA 128x256 (2 heads), warp tile 64x64, 8 warps
#define BM 128
#define BN 256
#define BK 32
#define NCH (FIN / BK)    // 32
#define NSTAGE 3
#define AS_STRIDE 40      // halves per A row (32 + 8 pad)
#define BS_STRIDE 264     // halves per B row (256 + 8 pad)
#define A_BYTES (BM * AS_STRIDE * 2)           // 10240
#define B_BYTES (BK * BS_STRIDE * 2)           // 16896
#define STAGE_BYTES (A_BYTES + B_BYTES)        // 27136
#define RED_OFF  (NSTAGE * STAGE_BYTES)        // 81408
#define BIAS_OFF (RED_OFF + 8192)              // 89600 (sRed = 2048 floats)
#define SMEM_BYTES (BIAS_OFF + 3072)           // 92672

// ---------------------------------------------------------------------------
// Scratch (device globals — no allocs allowed)
// ---------------------------------------------------------------------------
__device__ __half g_hh[(size_t)NH * NN * FOUT];   // 16 MB (h in fp16)
__device__ float g_sd[NH * NN];
__device__ float g_ss[NH * NN];
__device__ __half g_Xh[(size_t)NN * FIN];         // 16 MB
__device__ __half g_Wh[(size_t)NH * FIN * FOUT];  // 2 MB  [h][k][n]

// ---------------------------------------------------------------------------
// helpers
// ---------------------------------------------------------------------------
__device__ __forceinline__ uint32_t smem_u32(const void* p) {
    uint32_t a;
    asm("{ .reg .u64 t; cvta.to.shared.u64 t, %1; cvt.u32.u64 %0, t; }" : "=r"(a) : "l"(p));
    return a;
}
__device__ __forceinline__ void cpasync16(uint32_t dst, const void* src) {
    asm volatile("cp.async.cg.shared.global [%0], [%1], 16;"
                 :: "r"(dst), "l"(__cvta_generic_to_global(src)) : "memory");
}
__device__ __forceinline__ void ldsm_x4(uint32_t* r, uint32_t addr) {
    asm volatile("ldmatrix.sync.aligned.m8n8.x4.shared.b16 {%0,%1,%2,%3}, [%4];"
                 : "=r"(r[0]), "=r"(r[1]), "=r"(r[2]), "=r"(r[3]) : "r"(addr));
}
__device__ __forceinline__ void ldsm_x4_t(uint32_t* r, uint32_t addr) {
    asm volatile("ldmatrix.sync.aligned.m8n8.x4.trans.shared.b16 {%0,%1,%2,%3}, [%4];"
                 : "=r"(r[0]), "=r"(r[1]), "=r"(r[2]), "=r"(r[3]) : "r"(addr));
}
__device__ __forceinline__ void mma_f16(float* d, const uint32_t* a, const uint32_t* b) {
    asm volatile(
        "mma.sync.aligned.m16n8k16.row.col.f32.f16.f16.f32 "
        "{%0,%1,%2,%3}, {%4,%5,%6,%7}, {%8,%9}, {%0,%1,%2,%3};"
        : "+f"(d[0]), "+f"(d[1]), "+f"(d[2]), "+f"(d[3])
        : "r"(a[0]), "r"(a[1]), "r"(a[2]), "r"(a[3]), "r"(b[0]), "r"(b[1]));
}

// ---------------------------------------------------------------------------
// Prep 1: X -> fp16
// ---------------------------------------------------------------------------
__global__ __launch_bounds__(256) void conv_x(const float* __restrict__ X) {
    size_t i = (size_t)blockIdx.x * 256 + threadIdx.x;
    float4 v = ((const float4*)X)[i];
    __half h[4] = { __float2half_rn(v.x), __float2half_rn(v.y),
                    __float2half_rn(v.z), __float2half_rn(v.w) };
    *(uint2*)(g_Xh + i * 4) = *(uint2*)h;
}

// ---------------------------------------------------------------------------
// Prep 2: W -> fp16 (layout preserved: [h][k][n])
// ---------------------------------------------------------------------------
__global__ __launch_bounds__(256) void conv_w(const float* __restrict__ W) {
    size_t i = (size_t)blockIdx.x * 256 + threadIdx.x;
    float4 v = ((const float4*)W)[i];
    __half h[4] = { __float2half_rn(v.x), __float2half_rn(v.y),
                    __float2half_rn(v.z), __float2half_rn(v.w) };
    *(uint2*)(g_Wh + i * 4) = *(uint2*)h;
}

// ---------------------------------------------------------------------------
// Main GEMM: mma.sync fp16, 3-stage cp.async, 128x256 CTA, 64x64 warp tiles.
// Direct register epilogue (no Cs roundtrip): bias + fp16 h store +
// quad-shfl/smem-reduced s_dst/s_src dots.
// grid (NN/128 = 64, NH/2 = 4), 256 threads.
// ---------------------------------------------------------------------------
__global__ __launch_bounds__(256, 1) void gat_gemm_mma(
    const float* __restrict__ bW, const float* __restrict__ av)
{
    extern __shared__ char smem[];
    const uint32_t sb = smem_u32(smem);
    float* sRed  = (float*)(smem + RED_OFF);    // [ch][g][row][2] = 2048 floats
    float* sBias = (float*)(smem + BIAS_OFF);   // 256
    float* sAd   = sBias + 256;
    float* sAs   = sAd + 256;

    const int tid = threadIdx.x, wid = tid >> 5, lane = tid & 31;
    const int m0  = blockIdx.x * BM;
    const int hd0 = blockIdx.y * 2;
    const int mw  = (wid & 1) * 64;       // warp m offset
    const int nq  = wid >> 1;             // 0..3
    const int nw  = nq * 64;              // warp n offset (within 256)
    const int g   = nq >> 1;              // head within pair
    const int ch  = nq & 1;               // 64-col half within head

    // stage bias / attention vectors (read only in epilogue, post-sync)
    {
        int h = hd0 + (tid >> 7), c = tid & 127;
        sBias[tid] = bW[h * FOUT + c];
        sAd[tid]   = av[h * 2 * FOUT + c];
        sAs[tid]   = av[h * 2 * FOUT + FOUT + c];
    }

    float acc[4][8][4];
#pragma unroll
    for (int a = 0; a < 4; a++)
#pragma unroll
        for (int b = 0; b < 8; b++)
#pragma unroll
            for (int c = 0; c < 4; c++) acc[a][b][c] = 0.f;

    // per-thread load coords
    const int a_row = tid >> 2, a_col = (tid & 3) * 8;     // 64 rows/pass, 2 passes
    const int b_row = tid >> 5, b_col = (tid & 31) * 8;    // 8 rows/pass, 4 passes
    const int b_hd  = hd0 + (b_col >> 7);
    const int b_cc  = b_col & 127;

    auto issue_loads = [&](int i) {
        const int kk = i * BK;
        const uint32_t as = sb + (i % NSTAGE) * STAGE_BYTES;
        const uint32_t bs = as + A_BYTES;
#pragma unroll
        for (int p = 0; p < 2; p++) {
            int row = a_row + p * 64;
            cpasync16(as + (row * AS_STRIDE + a_col) * 2,
                      g_Xh + (size_t)(m0 + row) * FIN + kk + a_col);
        }
#pragma unroll
        for (int p = 0; p < 4; p++) {
            int row = b_row + p * 8;
            cpasync16(bs + (row * BS_STRIDE + b_col) * 2,
                      g_Wh + ((size_t)b_hd * FIN + kk + row) * FOUT + b_cc);
        }
        asm volatile("cp.async.commit_group;" ::: "memory");
    };

    issue_loads(0);
    issue_loads(1);

    const int lr = lane & 15, lh = (lane >> 4) << 3;   // ldmatrix addressing

    for (int i = 0; i < NCH; i++) {
        asm volatile("cp.async.wait_group 1;" ::: "memory");
        __syncthreads();
        if (i + 2 < NCH) issue_loads(i + 2);
        else asm volatile("cp.async.commit_group;" ::: "memory");  // keep count

        const uint32_t as = sb + (i % NSTAGE) * STAGE_BYTES;
        const uint32_t bs = as + A_BYTES;

#pragma unroll
        for (int ks = 0; ks < 2; ks++) {
            const int k16 = ks * 16;
            uint32_t afr[4][4], bfr[4][4];
#pragma unroll
            for (int mt = 0; mt < 4; mt++)
                ldsm_x4(afr[mt], as + ((mw + mt * 16 + lr) * AS_STRIDE + k16 + lh) * 2);
#pragma unroll
            for (int nt2 = 0; nt2 < 4; nt2++)
                ldsm_x4_t(bfr[nt2], bs + ((k16 + lr) * BS_STRIDE + nw + nt2 * 16 + lh) * 2);
#pragma unroll
            for (int mt = 0; mt < 4; mt++)
#pragma unroll
                for (int nt = 0; nt < 8; nt++)
                    mma_f16(acc[mt][nt], afr[mt], &bfr[nt >> 1][(nt & 1) * 2]);
        }
    }

    // ---- direct register epilogue ----
    const int lq = lane >> 2, qt = lane & 3;
    const int hd = hd0 + g;
    const float* bb = sBias + g * 128;
    const float* aa = sAd + g * 128;
    const float* ss = sAs + g * 128;

#pragma unroll
    for (int mt = 0; mt < 4; mt++) {
#pragma unroll
        for (int s = 0; s < 2; s++) {
            const int row = mw + mt * 16 + lq + s * 8;
            __half* dst = g_hh + ((size_t)hd * NN + m0 + row) * FOUT;
            float pd = 0.f, ps = 0.f;
#pragma unroll
            for (int nt = 0; nt < 8; nt++) {
                int col = ch * 64 + nt * 8 + qt * 2;
                float t0 = acc[mt][nt][2 * s + 0] + bb[col];
                float t1 = acc[mt][nt][2 * s + 1] + bb[col + 1];
                pd += t0 * aa[col] + t1 * aa[col + 1];
                ps += t0 * ss[col] + t1 * ss[col + 1];
                *(__half2*)(dst + col) = __floats2half2_rn(t0, t1);
            }
            pd += __shfl_xor_sync(0xffffffffu, pd, 1);
            pd += __shfl_xor_sync(0xffffffffu, pd, 2);
            ps += __shfl_xor_sync(0xffffffffu, ps, 1);
            ps += __shfl_xor_sync(0xffffffffu, ps, 2);
            if (qt == 0) {
                sRed[((ch * 2 + g) * 128 + row) * 2 + 0] = pd;
                sRed[((ch * 2 + g) * 128 + row) * 2 + 1] = ps;
            }
        }
    }
    __syncthreads();
    {
        const int gg = tid >> 7, row = tid & 127;
        float pd = sRed[((0 * 2 + gg) * 128 + row) * 2 + 0]
                 + sRed[((1 * 2 + gg) * 128 + row) * 2 + 0];
        float ps = sRed[((0 * 2 + gg) * 128 + row) * 2 + 1]
                 + sRed[((1 * 2 + gg) * 128 + row) * 2 + 1];
        g_sd[(hd0 + gg) * NN + m0 + row] = pd;
        g_ss[(hd0 + gg) * NN + m0 + row] = ps;
    }
}

// ---------------------------------------------------------------------------
// Attention softmax + weighted gather (h in fp16), 2 neighbors per iteration.
// ---------------------------------------------------------------------------
__global__ __launch_bounds__(256) void gat_attn(
    const int* __restrict__ adj, const float* __restrict__ ba,
    float* __restrict__ out)
{
    const int n = blockIdx.x;
    const int w = threadIdx.x >> 5;
    const int lane = threadIdx.x & 31;

    const __half* Hh = g_hh + (size_t)w * NN * FOUT;

    int nbr = n;
    if (lane < DEG) nbr = adj[n * DEG + lane];

    float sdst = g_sd[w * NN + n];
    float score = -INFINITY;
    if (lane < DEG + 1) {
        float s = sdst + g_ss[w * NN + nbr] + ba[w];
        score = (s > 0.f) ? s : 0.2f * s;
    }
    float mx = score;
#pragma unroll
    for (int off = 16; off; off >>= 1)
        mx = fmaxf(mx, __shfl_xor_sync(0xffffffffu, mx, off));
    float e = (lane < DEG + 1) ? __expf(score - mx) : 0.f;
    float sum = e;
#pragma unroll
    for (int off = 16; off; off >>= 1)
        sum += __shfl_xor_sync(0xffffffffu, sum, off);
    float alpha = e / sum;

    // half-warp d-parallel gather: lanes 0-15 handle even d, 16-31 odd d
    const int half = lane >> 4, li = lane & 15;
    float a8[8] = {0.f, 0.f, 0.f, 0.f, 0.f, 0.f, 0.f, 0.f};
#pragma unroll
    for (int d = 0; d < DEG + 2; d += 2) {
        int dd = d + half;
        float ad = __shfl_sync(0xffffffffu, alpha, dd & 31);
        int idx  = __shfl_sync(0xffffffffu, nbr, dd & 31);
        if (dd < DEG + 1) {
            uint4 v = *(const uint4*)(Hh + (size_t)idx * FOUT + li * 8);
            float2 f0 = __half22float2(*(__half2*)&v.x);
            float2 f1 = __half22float2(*(__half2*)&v.y);
            float2 f2 = __half22float2(*(__half2*)&v.z);
            float2 f3 = __half22float2(*(__half2*)&v.w);
            a8[0] += ad * f0.x; a8[1] += ad * f0.y;
            a8[2] += ad * f1.x; a8[3] += ad * f1.y;
            a8[4] += ad * f2.x; a8[5] += ad * f2.y;
            a8[6] += ad * f3.x; a8[7] += ad * f3.y;
        }
    }
#pragma unroll
    for (int q = 0; q < 8; q++)
        a8[q] += __shfl_xor_sync(0xffffffffu, a8[q], 16);
    if (half == 0) {
        float* dst = out + (size_t)n * (NH * FOUT) + w * FOUT + li * 8;
        *(float4*)(dst + 0) = make_float4(a8[0], a8[1], a8[2], a8[3]);
        *(float4*)(dst + 4) = make_float4(a8[4], a8[5], a8[6], a8[7]);
    }
}

// ---------------------------------------------------------------------------
extern "C" void kernel_launch(void* const* d_in, const int* in_sizes, int n_in,
                              void* d_out, int out_size)
{
    const float* X   = (const float*)d_in[0];
    const int*   adj = (const int*)  d_in[1];
    const float* W   = (const float*)d_in[2];
    const float* bW  = (const float*)d_in[3];
    const float* av  = (const float*)d_in[4];
    const float* ba  = (const float*)d_in[5];
    float* out = (float*)d_out;

    cudaFuncSetAttribute(gat_gemm_mma,
                         cudaFuncAttributeMaxDynamicSharedMemorySize, SMEM_BYTES);

    conv_x<<<NN * FIN / 4 / 256, 256>>>(X);
    conv_w<<<NH * FIN * FOUT / 4 / 256, 256>>>(W);
    gat_gemm_mma<<<dim3(NN / BM, NH / 2), 256, SMEM_BYTES>>>(bW, av);
    gat_attn<<<NN, 256>>>(adj, ba, out);
}

// round 14
// speedup vs baseline: 6.9949x; 1.0383x over previous
#include <cuda_runtime.h>
#include <cuda_fp16.h>
#include <math.h>
#include <stdint.h>

// Problem constants
#define NN    8192
#define DEG   16
#define FIN   1024
#define FOUT  128
#define NH    8

// GEMM config: CTA 128x256 (2 heads), warp tile 64x64, 8 warps
#define BM 128
#define BN 256
#define BK 32
#define NCH (FIN / BK)    // 32
#define NSTAGE 3
#define AS_STRIDE 40      // halves per A row (32 + 8 pad)
#define BS_STRIDE 264     // halves per B row (256 + 8 pad)
#define A_BYTES (BM * AS_STRIDE * 2)           // 10240
#define B_BYTES (BK * BS_STRIDE * 2)           // 16896
#define STAGE_BYTES (A_BYTES + B_BYTES)        // 27136
#define RED_OFF  (NSTAGE * STAGE_BYTES)        // 81408
#define BIAS_OFF (RED_OFF + 8192)              // 89600 (sRed = 2048 floats)
#define SMEM_BYTES (BIAS_OFF + 3072)           // 92672

// ---------------------------------------------------------------------------
// Scratch (device globals — no allocs allowed)
// ---------------------------------------------------------------------------
__device__ __half g_hh[(size_t)NH * NN * FOUT];   // 16 MB (h in fp16)
__device__ float g_sd[NH * NN];
__device__ float g_ss[NH * NN];
__device__ __half g_Xh[(size_t)NN * FIN];         // 16 MB
__device__ __half g_Wh[(size_t)NH * FIN * FOUT];  // 2 MB  [h][k][n]

// ---------------------------------------------------------------------------
// helpers
// ---------------------------------------------------------------------------
__device__ __forceinline__ uint32_t smem_u32(const void* p) {
    uint32_t a;
    asm("{ .reg .u64 t; cvta.to.shared.u64 t, %1; cvt.u32.u64 %0, t; }" : "=r"(a) : "l"(p));
    return a;
}
__device__ __forceinline__ void cpasync16(uint32_t dst, const void* src) {
    asm volatile("cp.async.cg.shared.global [%0], [%1], 16;"
                 :: "r"(dst), "l"(__cvta_generic_to_global(src)) : "memory");
}
__device__ __forceinline__ void ldsm_x4(uint32_t* r, uint32_t addr) {
    asm volatile("ldmatrix.sync.aligned.m8n8.x4.shared.b16 {%0,%1,%2,%3}, [%4];"
                 : "=r"(r[0]), "=r"(r[1]), "=r"(r[2]), "=r"(r[3]) : "r"(addr));
}
__device__ __forceinline__ void ldsm_x4_t(uint32_t* r, uint32_t addr) {
    asm volatile("ldmatrix.sync.aligned.m8n8.x4.trans.shared.b16 {%0,%1,%2,%3}, [%4];"
                 : "=r"(r[0]), "=r"(r[1]), "=r"(r[2]), "=r"(r[3]) : "r"(addr));
}
__device__ __forceinline__ void mma_f16(float* d, const uint32_t* a, const uint32_t* b) {
    asm volatile(
        "mma.sync.aligned.m16n8k16.row.col.f32.f16.f16.f32 "
        "{%0,%1,%2,%3}, {%4,%5,%6,%7}, {%8,%9}, {%0,%1,%2,%3};"
        : "+f"(d[0]), "+f"(d[1]), "+f"(d[2]), "+f"(d[3])
        : "r"(a[0]), "r"(a[1]), "r"(a[2]), "r"(a[3]), "r"(b[0]), "r"(b[1]));
}

// ---------------------------------------------------------------------------
// Prep (merged): X -> fp16 and W -> fp16, branch on blockIdx.
// X: NN*FIN/4 = 2097152 float4s -> 8192 blocks. W: 1048576/4... = 1024 blocks.
// ---------------------------------------------------------------------------
#define XBLK (NN * FIN / 4 / 256)                 // 8192
#define WBLK (NH * FIN * FOUT / 4 / 256)          // 1024
__global__ __launch_bounds__(256) void conv_xw(
    const float* __restrict__ X, const float* __restrict__ W)
{
    int b = blockIdx.x;
    if (b < XBLK) {
        size_t i = (size_t)b * 256 + threadIdx.x;
        float4 v = ((const float4*)X)[i];
        __half h[4] = { __float2half_rn(v.x), __float2half_rn(v.y),
                        __float2half_rn(v.z), __float2half_rn(v.w) };
        *(uint2*)(g_Xh + i * 4) = *(uint2*)h;
    } else {
        size_t i = (size_t)(b - XBLK) * 256 + threadIdx.x;
        float4 v = ((const float4*)W)[i];
        __half h[4] = { __float2half_rn(v.x), __float2half_rn(v.y),
                        __float2half_rn(v.z), __float2half_rn(v.w) };
        *(uint2*)(g_Wh + i * 4) = *(uint2*)h;
    }
}

// ---------------------------------------------------------------------------
// Main GEMM: mma.sync fp16, 3-stage cp.async, 128x256 CTA, 64x64 warp tiles.
// Direct register epilogue: bias + fp16 h store + reduced s_dst/s_src dots.
// grid (NN/128 = 64, NH/2 = 4), 256 threads.  (unchanged from R12)
// ---------------------------------------------------------------------------
__global__ __launch_bounds__(256, 1) void gat_gemm_mma(
    const float* __restrict__ bW, const float* __restrict__ av)
{
    extern __shared__ char smem[];
    const uint32_t sb = smem_u32(smem);
    float* sRed  = (float*)(smem + RED_OFF);    // [ch][g][row][2] = 2048 floats
    float* sBias = (float*)(smem + BIAS_OFF);   // 256
    float* sAd   = sBias + 256;
    float* sAs   = sAd + 256;

    const int tid = threadIdx.x, wid = tid >> 5, lane = tid & 31;
    const int m0  = blockIdx.x * BM;
    const int hd0 = blockIdx.y * 2;
    const int mw  = (wid & 1) * 64;       // warp m offset
    const int nq  = wid >> 1;             // 0..3
    const int nw  = nq * 64;              // warp n offset (within 256)
    const int g   = nq >> 1;              // head within pair
    const int ch  = nq & 1;               // 64-col half within head

    {
        int h = hd0 + (tid >> 7), c = tid & 127;
        sBias[tid] = bW[h * FOUT + c];
        sAd[tid]   = av[h * 2 * FOUT + c];
        sAs[tid]   = av[h * 2 * FOUT + FOUT + c];
    }

    float acc[4][8][4];
#pragma unroll
    for (int a = 0; a < 4; a++)
#pragma unroll
        for (int b = 0; b < 8; b++)
#pragma unroll
            for (int c = 0; c < 4; c++) acc[a][b][c] = 0.f;

    const int a_row = tid >> 2, a_col = (tid & 3) * 8;
    const int b_row = tid >> 5, b_col = (tid & 31) * 8;
    const int b_hd  = hd0 + (b_col >> 7);
    const int b_cc  = b_col & 127;

    auto issue_loads = [&](int i) {
        const int kk = i * BK;
        const uint32_t as = sb + (i % NSTAGE) * STAGE_BYTES;
        const uint32_t bs = as + A_BYTES;
#pragma unroll
        for (int p = 0; p < 2; p++) {
            int row = a_row + p * 64;
            cpasync16(as + (row * AS_STRIDE + a_col) * 2,
                      g_Xh + (size_t)(m0 + row) * FIN + kk + a_col);
        }
#pragma unroll
        for (int p = 0; p < 4; p++) {
            int row = b_row + p * 8;
            cpasync16(bs + (row * BS_STRIDE + b_col) * 2,
                      g_Wh + ((size_t)b_hd * FIN + kk + row) * FOUT + b_cc);
        }
        asm volatile("cp.async.commit_group;" ::: "memory");
    };

    issue_loads(0);
    issue_loads(1);

    const int lr = lane & 15, lh = (lane >> 4) << 3;

    for (int i = 0; i < NCH; i++) {
        asm volatile("cp.async.wait_group 1;" ::: "memory");
        __syncthreads();
        if (i + 2 < NCH) issue_loads(i + 2);
        else asm volatile("cp.async.commit_group;" ::: "memory");

        const uint32_t as = sb + (i % NSTAGE) * STAGE_BYTES;
        const uint32_t bs = as + A_BYTES;

#pragma unroll
        for (int ks = 0; ks < 2; ks++) {
            const int k16 = ks * 16;
            uint32_t afr[4][4], bfr[4][4];
#pragma unroll
            for (int mt = 0; mt < 4; mt++)
                ldsm_x4(afr[mt], as + ((mw + mt * 16 + lr) * AS_STRIDE + k16 + lh) * 2);
#pragma unroll
            for (int nt2 = 0; nt2 < 4; nt2++)
                ldsm_x4_t(bfr[nt2], bs + ((k16 + lr) * BS_STRIDE + nw + nt2 * 16 + lh) * 2);
#pragma unroll
            for (int mt = 0; mt < 4; mt++)
#pragma unroll
                for (int nt = 0; nt < 8; nt++)
                    mma_f16(acc[mt][nt], afr[mt], &bfr[nt >> 1][(nt & 1) * 2]);
        }
    }

    // ---- direct register epilogue ----
    const int lq = lane >> 2, qt = lane & 3;
    const int hd = hd0 + g;
    const float* bb = sBias + g * 128;
    const float* aa = sAd + g * 128;
    const float* ss = sAs + g * 128;

#pragma unroll
    for (int mt = 0; mt < 4; mt++) {
#pragma unroll
        for (int s = 0; s < 2; s++) {
            const int row = mw + mt * 16 + lq + s * 8;
            __half* dst = g_hh + ((size_t)hd * NN + m0 + row) * FOUT;
            float pd = 0.f, ps = 0.f;
#pragma unroll
            for (int nt = 0; nt < 8; nt++) {
                int col = ch * 64 + nt * 8 + qt * 2;
                float t0 = acc[mt][nt][2 * s + 0] + bb[col];
                float t1 = acc[mt][nt][2 * s + 1] + bb[col + 1];
                pd += t0 * aa[col] + t1 * aa[col + 1];
                ps += t0 * ss[col] + t1 * ss[col + 1];
                *(__half2*)(dst + col) = __floats2half2_rn(t0, t1);
            }
            pd += __shfl_xor_sync(0xffffffffu, pd, 1);
            pd += __shfl_xor_sync(0xffffffffu, pd, 2);
            ps += __shfl_xor_sync(0xffffffffu, ps, 1);
            ps += __shfl_xor_sync(0xffffffffu, ps, 2);
            if (qt == 0) {
                sRed[((ch * 2 + g) * 128 + row) * 2 + 0] = pd;
                sRed[((ch * 2 + g) * 128 + row) * 2 + 1] = ps;
            }
        }
    }
    __syncthreads();
    {
        const int gg = tid >> 7, row = tid & 127;
        float pd = sRed[((0 * 2 + gg) * 128 + row) * 2 + 0]
                 + sRed[((1 * 2 + gg) * 128 + row) * 2 + 0];
        float ps = sRed[((0 * 2 + gg) * 128 + row) * 2 + 1]
                 + sRed[((1 * 2 + gg) * 128 + row) * 2 + 1];
        g_sd[(hd0 + gg) * NN + m0 + row] = pd;
        g_ss[(hd0 + gg) * NN + m0 + row] = ps;
    }
}

// ---------------------------------------------------------------------------
// Attention v3: warp = (node, 2 heads); half-warp per head; lane owns 8 cols.
// No idle lanes, no cross-lane output reduce. grid = NN/2, block 256.
// ---------------------------------------------------------------------------
__global__ __launch_bounds__(256) void gat_attn(
    const int* __restrict__ adj, const float* __restrict__ ba,
    float* __restrict__ out)
{
    const int wid  = threadIdx.x >> 5;
    const int lane = threadIdx.x & 31;
    const int n    = blockIdx.x * 2 + (wid >> 2);   // 2 nodes per block
    const int half = lane >> 4, li = lane & 15;
    const int hd   = ((wid & 3) << 1) + half;       // head 0..7

    const __half* Hh = g_hh + (size_t)hd * NN * FOUT;

    // neighbor li (every lane holds one of the 16 neighbors)
    const int nbr = adj[n * DEG + li];

    const float sdst = g_sd[hd * NN + n];
    const float bah  = ba[hd];

    // neighbor scores (16 lanes) + uniform self score
    float s = sdst + g_ss[hd * NN + nbr] + bah;
    float score = (s > 0.f) ? s : 0.2f * s;
    float s2 = sdst + g_ss[hd * NN + n] + bah;
    float sself = (s2 > 0.f) ? s2 : 0.2f * s2;

    // softmax over 17 (16-lane reduce + self term)
    float mx = score;
#pragma unroll
    for (int off = 8; off; off >>= 1)
        mx = fmaxf(mx, __shfl_xor_sync(0xffffffffu, mx, off));
    mx = fmaxf(mx, sself);
    float e = __expf(score - mx);
    float eself = __expf(sself - mx);
    float sum = e;
#pragma unroll
    for (int off = 8; off; off >>= 1)
        sum += __shfl_xor_sync(0xffffffffu, sum, off);
    sum += eself;
    const float inv = 1.0f / sum;
    const float alpha = e * inv;
    const float aself = eself * inv;

    // gather: 16 neighbor rows + self row; each lane loads 16B (8 cols)
    float a8[8] = {0.f, 0.f, 0.f, 0.f, 0.f, 0.f, 0.f, 0.f};
    const size_t coff = (size_t)li * 8;
#pragma unroll
    for (int d = 0; d < DEG; d++) {
        const int src = half * 16 + d;
        float ad = __shfl_sync(0xffffffffu, alpha, src);
        int idx  = __shfl_sync(0xffffffffu, nbr, src);
        uint4 v = *(const uint4*)(Hh + (size_t)idx * FOUT + coff);
        float2 f0 = __half22float2(*(__half2*)&v.x);
        float2 f1 = __half22float2(*(__half2*)&v.y);
        float2 f2 = __half22float2(*(__half2*)&v.z);
        float2 f3 = __half22float2(*(__half2*)&v.w);
        a8[0] += ad * f0.x; a8[1] += ad * f0.y;
        a8[2] += ad * f1.x; a8[3] += ad * f1.y;
        a8[4] += ad * f2.x; a8[5] += ad * f2.y;
        a8[6] += ad * f3.x; a8[7] += ad * f3.y;
    }
    {   // self row
        uint4 v = *(const uint4*)(Hh + (size_t)n * FOUT + coff);
        float2 f0 = __half22float2(*(__half2*)&v.x);
        float2 f1 = __half22float2(*(__half2*)&v.y);
        float2 f2 = __half22float2(*(__half2*)&v.z);
        float2 f3 = __half22float2(*(__half2*)&v.w);
        a8[0] += aself * f0.x; a8[1] += aself * f0.y;
        a8[2] += aself * f1.x; a8[3] += aself * f1.y;
        a8[4] += aself * f2.x; a8[5] += aself * f2.y;
        a8[6] += aself * f3.x; a8[7] += aself * f3.y;
    }

    float* dst = out + (size_t)n * (NH * FOUT) + hd * FOUT + li * 8;
    *(float4*)(dst + 0) = make_float4(a8[0], a8[1], a8[2], a8[3]);
    *(float4*)(dst + 4) = make_float4(a8[4], a8[5], a8[6], a8[7]);
}

// ---------------------------------------------------------------------------
extern "C" void kernel_launch(void* const* d_in, const int* in_sizes, int n_in,
                              void* d_out, int out_size)
{
    const float* X   = (const float*)d_in[0];
    const int*   adj = (const int*)  d_in[1];
    const float* W   = (const float*)d_in[2];
    const float* bW  = (const float*)d_in[3];
    const float* av  = (const float*)d_in[4];
    const float* ba  = (const float*)d_in[5];
    float* out = (float*)d_out;

    cudaFuncSetAttribute(gat_gemm_mma,
                         cudaFuncAttributeMaxDynamicSharedMemorySize, SMEM_BYTES);

    conv_xw<<<XBLK + WBLK, 256>>>(X, W);
    gat_gemm_mma<<<dim3(NN / BM, NH / 2), 256, SMEM_BYTES>>>(bW, av);
    gat_attn<<<NN / 2, 256>>>(adj, ba, out);
}

// round 15
// speedup vs baseline: 7.7149x; 1.1029x over previous
#include <cuda_runtime.h>
#include <cuda_fp16.h>
#include <math.h>
#include <stdint.h>

// Problem constants
#define NN    8192
#define DEG   16
#define FIN   1024
#define FOUT  128
#define NH    8

// GEMM config: CTA 64x128 (one head), 4 warps, warp tile 32x64
#define BM 64
#define BN 128
#define BK 32
#define NCH (FIN / BK)    // 32
#define NSTAGE 4
#define AS_STRIDE 40      // halves per A row (32 + 8 pad)
#define BS_STRIDE 136     // halves per B row (128 + 8 pad)
#define A_BYTES (BM * AS_STRIDE * 2)           // 5120
#define B_BYTES (BK * BS_STRIDE * 2)           // 8704
#define STAGE_BYTES (A_BYTES + B_BYTES)        // 13824
#define RED_OFF  (NSTAGE * STAGE_BYTES)        // 55296  (sRed: 256 floats)
#define BIAS_OFF (RED_OFF + 1024)              // 56320  (bias/ad/as: 384 floats)
#define SMEM_BYTES (BIAS_OFF + 1536)           // 57856

// ---------------------------------------------------------------------------
// Scratch (device globals — no allocs allowed)
// ---------------------------------------------------------------------------
__device__ __half g_hh[(size_t)NH * NN * FOUT];   // 16 MB (h in fp16)
__device__ float g_sd[NH * NN];
__device__ float g_ss[NH * NN];
__device__ __half g_Xh[(size_t)NN * FIN];         // 16 MB
__device__ __half g_Wh[(size_t)NH * FIN * FOUT];  // 2 MB  [h][k][n]

// ---------------------------------------------------------------------------
// helpers
// ---------------------------------------------------------------------------
__device__ __forceinline__ uint32_t smem_u32(const void* p) {
    uint32_t a;
    asm("{ .reg .u64 t; cvta.to.shared.u64 t, %1; cvt.u32.u64 %0, t; }" : "=r"(a) : "l"(p));
    return a;
}
__device__ __forceinline__ void cpasync16(uint32_t dst, const void* src) {
    asm volatile("cp.async.cg.shared.global [%0], [%1], 16;"
                 :: "r"(dst), "l"(__cvta_generic_to_global(src)) : "memory");
}
__device__ __forceinline__ void ldsm_x4(uint32_t* r, uint32_t addr) {
    asm volatile("ldmatrix.sync.aligned.m8n8.x4.shared.b16 {%0,%1,%2,%3}, [%4];"
                 : "=r"(r[0]), "=r"(r[1]), "=r"(r[2]), "=r"(r[3]) : "r"(addr));
}
__device__ __forceinline__ void ldsm_x4_t(uint32_t* r, uint32_t addr) {
    asm volatile("ldmatrix.sync.aligned.m8n8.x4.trans.shared.b16 {%0,%1,%2,%3}, [%4];"
                 : "=r"(r[0]), "=r"(r[1]), "=r"(r[2]), "=r"(r[3]) : "r"(addr));
}
__device__ __forceinline__ void mma_f16(float* d, const uint32_t* a, const uint32_t* b) {
    asm volatile(
        "mma.sync.aligned.m16n8k16.row.col.f32.f16.f16.f32 "
        "{%0,%1,%2,%3}, {%4,%5,%6,%7}, {%8,%9}, {%0,%1,%2,%3};"
        : "+f"(d[0]), "+f"(d[1]), "+f"(d[2]), "+f"(d[3])
        : "r"(a[0]), "r"(a[1]), "r"(a[2]), "r"(a[3]), "r"(b[0]), "r"(b[1]));
}

// ---------------------------------------------------------------------------
// Prep (merged): X -> fp16 and W -> fp16, 2 float4s per thread for MLP.
// X: 2097152 float4s -> 4096 blocks of 512. W: 262144 float4s -> 512 blocks.
// ---------------------------------------------------------------------------
#define XBLK (NN * FIN / 4 / 512)                 // 4096
#define WBLK (NH * FIN * FOUT / 4 / 512)          // 512
__global__ __launch_bounds__(256) void conv_xw(
    const float* __restrict__ X, const float* __restrict__ W)
{
    int b = blockIdx.x;
    const float4* src;
    __half* dst;
    size_t base;
    if (b < XBLK) {
        base = (size_t)b * 512 + threadIdx.x;
        src = (const float4*)X;
        dst = g_Xh;
    } else {
        base = (size_t)(b - XBLK) * 512 + threadIdx.x;
        src = (const float4*)W;
        dst = g_Wh;
    }
    float4 v0 = src[base];
    float4 v1 = src[base + 256];
    __half h0[4] = { __float2half_rn(v0.x), __float2half_rn(v0.y),
                     __float2half_rn(v0.z), __float2half_rn(v0.w) };
    __half h1[4] = { __float2half_rn(v1.x), __float2half_rn(v1.y),
                     __float2half_rn(v1.z), __float2half_rn(v1.w) };
    *(uint2*)(dst + base * 4)         = *(uint2*)h0;
    *(uint2*)(dst + (base + 256) * 4) = *(uint2*)h1;
}

// ---------------------------------------------------------------------------
// Main GEMM: mma.sync fp16, 4-stage cp.async, 64x128 CTA, 32x64 warp tiles.
// grid (NN/64 = 128, NH = 8) = 1024 CTAs, 128 threads, occ>=3.
// Direct register epilogue: bias + fp16 h store + reduced s_dst/s_src dots.
// ---------------------------------------------------------------------------
__global__ __launch_bounds__(128, 3) void gat_gemm_mma(
    const float* __restrict__ bW, const float* __restrict__ av)
{
    extern __shared__ char smem[];
    const uint32_t sb = smem_u32(smem);
    float* sRed  = (float*)(smem + RED_OFF);    // [nh][row][2] = 256 floats
    float* sBias = (float*)(smem + BIAS_OFF);   // 128
    float* sAd   = sBias + 128;
    float* sAs   = sAd + 128;

    const int tid = threadIdx.x, wid = tid >> 5, lane = tid & 31;
    const int m0 = blockIdx.x * BM;
    const int hd = blockIdx.y;
    const int mw = (wid & 1) * 32;        // warp m offset
    const int nh = wid >> 1;              // n half (0/1)
    const int nw = nh * 64;               // warp n offset

    {   // stage bias / attention vectors (used post-sync in epilogue)
        sBias[tid] = bW[hd * FOUT + tid];
        sAd[tid]   = av[hd * 2 * FOUT + tid];
        sAs[tid]   = av[hd * 2 * FOUT + FOUT + tid];
    }

    float acc[2][8][4];
#pragma unroll
    for (int a = 0; a < 2; a++)
#pragma unroll
        for (int b = 0; b < 8; b++)
#pragma unroll
            for (int c = 0; c < 4; c++) acc[a][b][c] = 0.f;

    // per-thread load coords (128 threads)
    const int a_row = tid >> 2, a_col = (tid & 3) * 8;     // 32 rows/pass, 2 passes
    const int b_row = tid >> 4, b_col = (tid & 15) * 8;    // 8 rows/pass, 4 passes

    auto issue_loads = [&](int i) {
        const int kk = i * BK;
        const uint32_t as = sb + (i % NSTAGE) * STAGE_BYTES;
        const uint32_t bs = as + A_BYTES;
#pragma unroll
        for (int p = 0; p < 2; p++) {
            int row = a_row + p * 32;
            cpasync16(as + (row * AS_STRIDE + a_col) * 2,
                      g_Xh + (size_t)(m0 + row) * FIN + kk + a_col);
        }
#pragma unroll
        for (int p = 0; p < 4; p++) {
            int row = b_row + p * 8;
            cpasync16(bs + (row * BS_STRIDE + b_col) * 2,
                      g_Wh + ((size_t)hd * FIN + kk + row) * FOUT + b_col);
        }
        asm volatile("cp.async.commit_group;" ::: "memory");
    };

    issue_loads(0);
    issue_loads(1);
    issue_loads(2);

    const int lr = lane & 15, lh = (lane >> 4) << 3;   // ldmatrix addressing

    for (int i = 0; i < NCH; i++) {
        asm volatile("cp.async.wait_group 2;" ::: "memory");
        __syncthreads();
        if (i + 3 < NCH) issue_loads(i + 3);
        else asm volatile("cp.async.commit_group;" ::: "memory");  // keep count

        const uint32_t as = sb + (i % NSTAGE) * STAGE_BYTES;
        const uint32_t bs = as + A_BYTES;

#pragma unroll
        for (int ks = 0; ks < 2; ks++) {
            const int k16 = ks * 16;
            uint32_t afr[2][4], bfr[4][4];
#pragma unroll
            for (int mt = 0; mt < 2; mt++)
                ldsm_x4(afr[mt], as + ((mw + mt * 16 + lr) * AS_STRIDE + k16 + lh) * 2);
#pragma unroll
            for (int nt2 = 0; nt2 < 4; nt2++)
                ldsm_x4_t(bfr[nt2], bs + ((k16 + lr) * BS_STRIDE + nw + nt2 * 16 + lh) * 2);
#pragma unroll
            for (int mt = 0; mt < 2; mt++)
#pragma unroll
                for (int nt = 0; nt < 8; nt++)
                    mma_f16(acc[mt][nt], afr[mt], &bfr[nt >> 1][(nt & 1) * 2]);
        }
    }

    // ---- direct register epilogue ----
    const int lq = lane >> 2, qt = lane & 3;
    const float* bb = sBias;
    const float* aa = sAd;
    const float* ss = sAs;

#pragma unroll
    for (int mt = 0; mt < 2; mt++) {
#pragma unroll
        for (int s = 0; s < 2; s++) {
            const int row = mw + mt * 16 + lq + s * 8;
            __half* dst = g_hh + ((size_t)hd * NN + m0 + row) * FOUT;
            float pd = 0.f, ps = 0.f;
#pragma unroll
            for (int nt = 0; nt < 8; nt++) {
                int col = nw + nt * 8 + qt * 2;
                float t0 = acc[mt][nt][2 * s + 0] + bb[col];
                float t1 = acc[mt][nt][2 * s + 1] + bb[col + 1];
                pd += t0 * aa[col] + t1 * aa[col + 1];
                ps += t0 * ss[col] + t1 * ss[col + 1];
                *(__half2*)(dst + col) = __floats2half2_rn(t0, t1);
            }
            pd += __shfl_xor_sync(0xffffffffu, pd, 1);
            pd += __shfl_xor_sync(0xffffffffu, pd, 2);
            ps += __shfl_xor_sync(0xffffffffu, ps, 1);
            ps += __shfl_xor_sync(0xffffffffu, ps, 2);
            if (qt == 0) {
                sRed[(nh * 64 + row) * 2 + 0] = pd;
                sRed[(nh * 64 + row) * 2 + 1] = ps;
            }
        }
    }
    __syncthreads();
    if (tid < 64) {
        const int row = tid;
        float pd = sRed[row * 2 + 0] + sRed[(64 + row) * 2 + 0];
        float ps = sRed[row * 2 + 1] + sRed[(64 + row) * 2 + 1];
        g_sd[hd * NN + m0 + row] = pd;
        g_ss[hd * NN + m0 + row] = ps;
    }
}

// ---------------------------------------------------------------------------
// Attention v3: warp = (node, 2 heads); half-warp per head; lane owns 8 cols.
// ---------------------------------------------------------------------------
__global__ __launch_bounds__(256) void gat_attn(
    const int* __restrict__ adj, const float* __restrict__ ba,
    float* __restrict__ out)
{
    const int wid  = threadIdx.x >> 5;
    const int lane = threadIdx.x & 31;
    const int n    = blockIdx.x * 2 + (wid >> 2);   // 2 nodes per block
    const int half = lane >> 4, li = lane & 15;
    const int hd   = ((wid & 3) << 1) + half;       // head 0..7

    const __half* Hh = g_hh + (size_t)hd * NN * FOUT;

    const int nbr = adj[n * DEG + li];

    const float sdst = g_sd[hd * NN + n];
    const float bah  = ba[hd];

    float s = sdst + g_ss[hd * NN + nbr] + bah;
    float score = (s > 0.f) ? s : 0.2f * s;
    float s2 = sdst + g_ss[hd * NN + n] + bah;
    float sself = (s2 > 0.f) ? s2 : 0.2f * s2;

    float mx = score;
#pragma unroll
    for (int off = 8; off; off >>= 1)
        mx = fmaxf(mx, __shfl_xor_sync(0xffffffffu, mx, off));
    mx = fmaxf(mx, sself);
    float e = __expf(score - mx);
    float eself = __expf(sself - mx);
    float sum = e;
#pragma unroll
    for (int off = 8; off; off >>= 1)
        sum += __shfl_xor_sync(0xffffffffu, sum, off);
    sum += eself;
    const float inv = 1.0f / sum;
    const float alpha = e * inv;
    const float aself = eself * inv;

    float a8[8] = {0.f, 0.f, 0.f, 0.f, 0.f, 0.f, 0.f, 0.f};
    const size_t coff = (size_t)li * 8;
#pragma unroll
    for (int d = 0; d < DEG; d++) {
        const int src = half * 16 + d;
        float ad = __shfl_sync(0xffffffffu, alpha, src);
        int idx  = __shfl_sync(0xffffffffu, nbr, src);
        uint4 v = *(const uint4*)(Hh + (size_t)idx * FOUT + coff);
        float2 f0 = __half22float2(*(__half2*)&v.x);
        float2 f1 = __half22float2(*(__half2*)&v.y);
        float2 f2 = __half22float2(*(__half2*)&v.z);
        float2 f3 = __half22float2(*(__half2*)&v.w);
        a8[0] += ad * f0.x; a8[1] += ad * f0.y;
        a8[2] += ad * f1.x; a8[3] += ad * f1.y;
        a8[4] += ad * f2.x; a8[5] += ad * f2.y;
        a8[6] += ad * f3.x; a8[7] += ad * f3.y;
    }
    {   // self row
        uint4 v = *(const uint4*)(Hh + (size_t)n * FOUT + coff);
        float2 f0 = __half22float2(*(__half2*)&v.x);
        float2 f1 = __half22float2(*(__half2*)&v.y);
        float2 f2 = __half22float2(*(__half2*)&v.z);
        float2 f3 = __half22float2(*(__half2*)&v.w);
        a8[0] += aself * f0.x; a8[1] += aself * f0.y;
        a8[2] += aself * f1.x; a8[3] += aself * f1.y;
        a8[4] += aself * f2.x; a8[5] += aself * f2.y;
        a8[6] += aself * f3.x; a8[7] += aself * f3.y;
    }

    float* dst = out + (size_t)n * (NH * FOUT) + hd * FOUT + li * 8;
    *(float4*)(dst + 0) = make_float4(a8[0], a8[1], a8[2], a8[3]);
    *(float4*)(dst + 4) = make_float4(a8[4], a8[5], a8[6], a8[7]);
}

// ---------------------------------------------------------------------------
extern "C" void kernel_launch(void* const* d_in, const int* in_sizes, int n_in,
                              void* d_out, int out_size)
{
    const float* X   = (const float*)d_in[0];
    const int*   adj = (const int*)  d_in[1];
    const float* W   = (const float*)d_in[2];
    const float* bW  = (const float*)d_in[3];
    const float* av  = (const float*)d_in[4];
    const float* ba  = (const float*)d_in[5];
    float* out = (float*)d_out;

    cudaFuncSetAttribute(gat_gemm_mma,
                         cudaFuncAttributeMaxDynamicSharedMemorySize, SMEM_BYTES);

    conv_xw<<<XBLK + WBLK, 256>>>(X, W);
    gat_gemm_mma<<<dim3(NN / BM, NH), 128, SMEM_BYTES>>>(bW, av);
    gat_attn<<<NN / 2, 256>>>(adj, ba, out);
}